// round 6
// baseline (speedup 1.0000x reference)
#include <cuda_runtime.h>
#include <math.h>

// Problem constants (fixed by the reference)
#define NB 8
#define NC 512
#define NT 2048
#define N3C (3 * NC)
#define TEMP_INV (1.0f / 0.07f)
#define L2EPS 1e-12f

// ---------------------------------------------------------------------------
// Static scratch (no allocation allowed anywhere)
// ---------------------------------------------------------------------------
__device__ float g_qkv [(size_t)NB * N3C * NT];   // 1x1-conv output      (100.7 MB)
__device__ float g_qkv2[(size_t)NB * N3C * NT];   // after dwconv (+norm) (100.7 MB)
__device__ float g_attn[(size_t)NB * NT  * NT];   // scores / softmax     (134.2 MB)
__device__ float g_out [(size_t)NB * NC  * NT];   // attention output     ( 33.6 MB)

// ---------------------------------------------------------------------------
// Generic fp32 SGEMM: C[M,N] = alpha * op(A)[M,K] * op(B)[K,N]
//   TA: A stored as A[k*lda + m]  (i.e. logical A transposed in memory)
//   TB: B stored as B[n*ldb + k]
// Requires: M,N multiples of 128; K multiple of 8; 16B alignment (all satisfied).
// Block: 256 threads, 128x128 tile, BK=8, each thread computes 8x8.
// ---------------------------------------------------------------------------
template <bool TA, bool TB>
__global__ __launch_bounds__(256)
void sgemm_kernel(const float* __restrict__ A, const float* __restrict__ B,
                  float* __restrict__ C,
                  int M, int N, int K, int lda, int ldb, int ldc,
                  long sA, long sB, long sC, float alpha)
{
    const int bz = blockIdx.z;
    A += (long)bz * sA;
    B += (long)bz * sB;
    C += (long)bz * sC;

    __shared__ float As[8][128];
    __shared__ float Bs[8][128];

    const int bm  = blockIdx.y * 128;
    const int bn  = blockIdx.x * 128;
    const int tid = threadIdx.x;          // 0..255
    const int tx  = tid & 15;             // 0..15  -> N
    const int ty  = tid >> 4;             // 0..15  -> M

    float acc[8][8];
#pragma unroll
    for (int i = 0; i < 8; i++)
#pragma unroll
        for (int j = 0; j < 8; j++) acc[i][j] = 0.f;

    for (int bk = 0; bk < K; bk += 8) {
        // ---- load A tile into As[k][m] ----
        if (TA) {
            // A[k*lda + m]: contiguous along m
            const int k  = tid >> 5;            // 0..7
            const int m4 = (tid & 31) << 2;     // 0..124
            float4 v = *(const float4*)(A + (long)(bk + k) * lda + bm + m4);
            *(float4*)(&As[k][m4]) = v;
        } else {
            // A[m*lda + k]: contiguous along k
            const int m = tid >> 1;             // 0..127
            const int j = (tid & 1) << 2;       // 0 or 4
            float4 v = *(const float4*)(A + (long)(bm + m) * lda + bk + j);
            As[j + 0][m] = v.x; As[j + 1][m] = v.y;
            As[j + 2][m] = v.z; As[j + 3][m] = v.w;
        }
        // ---- load B tile into Bs[k][n] ----
        if (TB) {
            // B[n*ldb + k]: contiguous along k
            const int n = tid >> 1;             // 0..127
            const int j = (tid & 1) << 2;       // 0 or 4
            float4 v = *(const float4*)(B + (long)(bn + n) * ldb + bk + j);
            Bs[j + 0][n] = v.x; Bs[j + 1][n] = v.y;
            Bs[j + 2][n] = v.z; Bs[j + 3][n] = v.w;
        } else {
            // B[k*ldb + n]: contiguous along n
            const int k  = tid >> 5;            // 0..7
            const int n4 = (tid & 31) << 2;     // 0..124
            float4 v = *(const float4*)(B + (long)(bk + k) * ldb + bn + n4);
            *(float4*)(&Bs[k][n4]) = v;
        }
        __syncthreads();

#pragma unroll
        for (int k = 0; k < 8; k++) {
            float ar[8], br[8];
#pragma unroll
            for (int i = 0; i < 8; i++) ar[i] = As[k][ty * 8 + i];
#pragma unroll
            for (int j = 0; j < 8; j++) br[j] = Bs[k][tx * 8 + j];
#pragma unroll
            for (int i = 0; i < 8; i++)
#pragma unroll
                for (int j = 0; j < 8; j++)
                    acc[i][j] += ar[i] * br[j];
        }
        __syncthreads();
    }

    // ---- epilogue ----
#pragma unroll
    for (int i = 0; i < 8; i++) {
        const long m = bm + ty * 8 + i;
#pragma unroll
        for (int j = 0; j < 8; j += 4) {
            float4 v;
            v.x = alpha * acc[i][j + 0];
            v.y = alpha * acc[i][j + 1];
            v.z = alpha * acc[i][j + 2];
            v.w = alpha * acc[i][j + 3];
            *(float4*)(C + m * ldc + bn + tx * 8 + j) = v;
        }
    }
}

// ---------------------------------------------------------------------------
// Depthwise conv, kernel=3, padding=1 along T, per channel (3C channels).
// out[b,ch,t] = w[ch,0]*in[t-1] + w[ch,1]*in[t] + w[ch,2]*in[t+1]  (zero pad)
// ---------------------------------------------------------------------------
__global__ void dwconv3_kernel(const float* __restrict__ in,
                               const float* __restrict__ w,
                               float* __restrict__ out)
{
    const long total = (long)NB * N3C * NT;
    long idx = (long)blockIdx.x * blockDim.x + threadIdx.x;
    if (idx >= total) return;
    const int t  = (int)(idx % NT);
    const int ch = (int)((idx / NT) % N3C);

    const float w0 = w[ch * 3 + 0];
    const float w1 = w[ch * 3 + 1];
    const float w2 = w[ch * 3 + 2];

    const float xm = (t > 0)      ? in[idx - 1] : 0.f;
    const float x0 = in[idx];
    const float xp = (t < NT - 1) ? in[idx + 1] : 0.f;

    out[idx] = w0 * xm + w1 * x0 + w2 * xp;
}

// ---------------------------------------------------------------------------
// L2-normalize q and k over the channel dim, per (b,t). In place on g_qkv2.
// ---------------------------------------------------------------------------
__global__ void l2norm_qk_kernel(float* __restrict__ qkv)
{
    const int b = blockIdx.y;
    const int t = blockIdx.x * 128 + threadIdx.x;
    float* base = qkv + (long)b * N3C * NT;

    float sq = 0.f, sk = 0.f;
    for (int c = 0; c < NC; c++) {
        float a = base[(long)c * NT + t];          sq += a * a;
        float d = base[(long)(NC + c) * NT + t];   sk += d * d;
    }
    const float iq = 1.f / fmaxf(sqrtf(sq), L2EPS);
    const float ik = 1.f / fmaxf(sqrtf(sk), L2EPS);
    for (int c = 0; c < NC; c++) {
        base[(long)c * NT + t]        *= iq;
        base[(long)(NC + c) * NT + t] *= ik;
    }
}

// ---------------------------------------------------------------------------
// Row softmax over T elements, in place. One 256-thread block per row.
// ---------------------------------------------------------------------------
__inline__ __device__ float warpMax(float v) {
#pragma unroll
    for (int o = 16; o; o >>= 1) v = fmaxf(v, __shfl_xor_sync(0xffffffffu, v, o));
    return v;
}
__inline__ __device__ float warpSum(float v) {
#pragma unroll
    for (int o = 16; o; o >>= 1) v += __shfl_xor_sync(0xffffffffu, v, o);
    return v;
}

__global__ void softmax_rows_kernel(float* __restrict__ attn)
{
    float* p = attn + (long)blockIdx.x * NT;
    const int tid  = threadIdx.x;      // 0..255
    const int lane = tid & 31;
    const int wid  = tid >> 5;         // 0..7
    __shared__ float red[8];

    float vals[8];
    float m = -1e30f;
#pragma unroll
    for (int i = 0; i < 8; i++) {
        vals[i] = p[tid + i * 256];
        m = fmaxf(m, vals[i]);
    }
    m = warpMax(m);
    if (lane == 0) red[wid] = m;
    __syncthreads();
    if (wid == 0) {
        float v = (lane < 8) ? red[lane] : -1e30f;   // FIX: no duplication
        v = warpMax(v);
        if (lane == 0) red[0] = v;
    }
    __syncthreads();
    m = red[0];
    __syncthreads();

    float s = 0.f;
#pragma unroll
    for (int i = 0; i < 8; i++) {
        vals[i] = __expf(vals[i] - m);
        s += vals[i];
    }
    s = warpSum(s);
    if (lane == 0) red[wid] = s;
    __syncthreads();
    if (wid == 0) {
        float v = (lane < 8) ? red[lane] : 0.f;      // FIX: was 4x overcount
        v = warpSum(v);
        if (lane == 0) red[0] = v;
    }
    __syncthreads();
    const float inv = 1.f / red[0];
#pragma unroll
    for (int i = 0; i < 8; i++) p[tid + i * 256] = vals[i] * inv;
}

// ---------------------------------------------------------------------------
// Launch
// ---------------------------------------------------------------------------
extern "C" void kernel_launch(void* const* d_in, const int* in_sizes, int n_in,
                              void* d_out, int out_size)
{
    const float* x      = (const float*)d_in[0];  // [B,C,T]
    const float* w_qkv  = (const float*)d_in[1];  // [3C,C,1]
    const float* w_dw   = (const float*)d_in[2];  // [3C,1,3]
    const float* w_proj = (const float*)d_in[3];  // [C,C,1]
    float* out = (float*)d_out;                   // [B,C,T]

    float *qkv, *qkv2, *attn, *aout;
    cudaGetSymbolAddress((void**)&qkv,  g_qkv);
    cudaGetSymbolAddress((void**)&qkv2, g_qkv2);
    cudaGetSymbolAddress((void**)&attn, g_attn);
    cudaGetSymbolAddress((void**)&aout, g_out);

    // 1) qkv = W_qkv @ x   : per batch [3C,C] x [C,T]
    {
        dim3 grid(NT / 128, N3C / 128, NB);
        sgemm_kernel<false, false><<<grid, 256>>>(
            w_qkv, x, qkv,
            N3C, NT, NC, /*lda=*/NC, /*ldb=*/NT, /*ldc=*/NT,
            /*sA=*/0, /*sB=*/(long)NC * NT, /*sC=*/(long)N3C * NT, 1.f);
    }

    // 2) depthwise conv k=3 pad=1 over T
    {
        const long total = (long)NB * N3C * NT;
        dwconv3_kernel<<<(unsigned)((total + 255) / 256), 256>>>(qkv, w_dw, qkv2);
    }

    // 3) L2-normalize q,k over channels (in place)
    {
        dim3 grid(NT / 128, NB);
        l2norm_qk_kernel<<<grid, 128>>>(qkv2);
    }

    // 4) S[t,s] = (1/TEMP) * sum_c q[c,t] k[c,s]   (A transposed)
    {
        const float* qp = qkv2;                         // q at channel offset 0
        const float* kp = qkv2 + (long)NC * NT;         // k
        dim3 grid(NT / 128, NT / 128, NB);
        sgemm_kernel<true, false><<<grid, 256>>>(
            qp, kp, attn,
            NT, NT, NC, /*lda=*/NT, /*ldb=*/NT, /*ldc=*/NT,
            /*sA=*/(long)N3C * NT, /*sB=*/(long)N3C * NT, /*sC=*/(long)NT * NT,
            TEMP_INV);
    }

    // 5) softmax over s (rows of attn), in place
    softmax_rows_kernel<<<NB * NT, 256>>>(attn);

    // 6) out[c,t] = sum_s v[c,s] * attn[t,s]   (B transposed)
    {
        const float* vp = qkv2 + (long)2 * NC * NT;
        dim3 grid(NT / 128, NC / 128, NB);
        sgemm_kernel<false, true><<<grid, 256>>>(
            vp, attn, aout,
            NC, NT, NT, /*lda=*/NT, /*ldb=*/NT, /*ldc=*/NT,
            /*sA=*/(long)N3C * NT, /*sB=*/(long)NT * NT, /*sC=*/(long)NC * NT,
            1.f);
    }

    // 7) final = W_proj @ out
    {
        dim3 grid(NT / 128, NC / 128, NB);
        sgemm_kernel<false, false><<<grid, 256>>>(
            w_proj, aout, out,
            NC, NT, NC, /*lda=*/NC, /*ldb=*/NT, /*ldc=*/NT,
            /*sA=*/0, /*sB=*/(long)NC * NT, /*sC=*/(long)NC * NT, 1.f);
    }
}

// round 8
// speedup vs baseline: 2.5897x; 2.5897x over previous
#include <cuda_runtime.h>
#include <cuda_bf16.h>
#include <math.h>
#include <stdint.h>

// Problem constants
#define NB 8
#define NC 512
#define NT 2048
#define N3C 1536
#define TEMP_INV (1.0f / 0.07f)
#define L2EPS 1e-12f

// ---------------------------------------------------------------------------
// Static scratch (no allocation allowed anywhere)
// ---------------------------------------------------------------------------
__device__ float g_qkv   [(size_t)NB * N3C * NT];
__device__ float g_qkv2  [(size_t)NB * N3C * NT];
__device__ float g_scores[(size_t)NB * NT  * NT];
__device__ float g_outT  [(size_t)NB * NT  * NC];
__device__ float g_qinv  [(size_t)NB * NT];
__device__ float g_kinv  [(size_t)NB * NT];

__device__ __nv_bfloat16 g_wq_h[(size_t)N3C * NC], g_wq_l[(size_t)N3C * NC];
__device__ __nv_bfloat16 g_wp_h[(size_t)NC  * NC], g_wp_l[(size_t)NC  * NC];
__device__ __nv_bfloat16 g_xT_h[(size_t)NB * NT * NC], g_xT_l[(size_t)NB * NT * NC];
__device__ __nv_bfloat16 g_qT_h[(size_t)NB * NT * NC], g_qT_l[(size_t)NB * NT * NC];
__device__ __nv_bfloat16 g_kT_h[(size_t)NB * NT * NC], g_kT_l[(size_t)NB * NT * NC];
__device__ __nv_bfloat16 g_v_h [(size_t)NB * NC * NT], g_v_l [(size_t)NB * NC * NT];
__device__ __nv_bfloat16 g_at_h[(size_t)NB * NT * NT], g_at_l[(size_t)NB * NT * NT];
__device__ __nv_bfloat16 g_oT_h[(size_t)NB * NT * NC], g_oT_l[(size_t)NB * NT * NC];

// ---------------------------------------------------------------------------
// PTX helpers (all baseline sm_80+ — NO 'a'-gated instructions)
// ---------------------------------------------------------------------------
__device__ __forceinline__ uint32_t s2u(const void* p) {
    uint32_t a;
    asm("{ .reg .u64 t; cvta.to.shared.u64 t, %1; cvt.u32.u64 %0, t; }"
        : "=r"(a) : "l"(p));
    return a;
}

__device__ __forceinline__ void cp16(uint32_t s, const void* g) {
    asm volatile("cp.async.cg.shared.global [%0], [%1], 16;" :: "r"(s), "l"(g));
}
#define CP_COMMIT() asm volatile("cp.async.commit_group;" ::: "memory")
#define CP_WAIT(n)  asm volatile("cp.async.wait_group %0;" :: "n"(n) : "memory")

__device__ __forceinline__ void ldsm4(uint32_t* r, uint32_t a) {
    asm volatile("ldmatrix.sync.aligned.m8n8.x4.shared.b16 {%0,%1,%2,%3}, [%4];"
                 : "=r"(r[0]), "=r"(r[1]), "=r"(r[2]), "=r"(r[3]) : "r"(a));
}
__device__ __forceinline__ void ldsm2(uint32_t* r, uint32_t a) {
    asm volatile("ldmatrix.sync.aligned.m8n8.x2.shared.b16 {%0,%1}, [%2];"
                 : "=r"(r[0]), "=r"(r[1]) : "r"(a));
}

__device__ __forceinline__ void mma16816(float* c, const uint32_t* a, const uint32_t* b) {
    asm volatile(
        "mma.sync.aligned.m16n8k16.row.col.f32.bf16.bf16.f32 "
        "{%0,%1,%2,%3}, {%4,%5,%6,%7}, {%8,%9}, {%0,%1,%2,%3};"
        : "+f"(c[0]), "+f"(c[1]), "+f"(c[2]), "+f"(c[3])
        : "r"(a[0]), "r"(a[1]), "r"(a[2]), "r"(a[3]), "r"(b[0]), "r"(b[1]));
}

// 128-byte-row XOR swizzle: rotate 16B chunk index by row%8
__device__ __forceinline__ uint32_t swz(uint32_t b) {
    return b ^ (((b >> 7) & 7) << 4);
}

// ---------------------------------------------------------------------------
// bf16x3 GEMM: C[M,N] = sum_k (Ah+Al)[m,k]*(Bh+Bl)[n,k], lo*lo dropped.
// A,B K-major (row stride = K). 128x128 CTA tile, BK=64, 3-stage cp.async.
// 8 warps: wm = wid&1 (2 x 64 rows), wn = wid>>1 (4 x 32 cols).
// ---------------------------------------------------------------------------
#define STAGE_BYTES 65536          // 4 tiles (Ah,Al,Bh,Bl) x 128x64 bf16
#define NSTAGE 3
#define GEMM_SMEM (NSTAGE * STAGE_BYTES)

__global__ __launch_bounds__(256, 1)
void gemm_bf16x3(const __nv_bfloat16* __restrict__ Ah, const __nv_bfloat16* __restrict__ Al,
                 const __nv_bfloat16* __restrict__ Bh, const __nv_bfloat16* __restrict__ Bl,
                 float* __restrict__ C, int K, int ldc,
                 long sA, long sB, long sC)
{
    extern __shared__ __align__(1024) char smem[];
    const uint32_t sb = s2u(smem);
    const int tid  = threadIdx.x;
    const int lane = tid & 31;
    const int wid  = tid >> 5;
    const int wm   = wid & 1;          // 0..1
    const int wn   = wid >> 1;         // 0..3
    const long bm  = (long)blockIdx.y * 128;
    const long bn  = (long)blockIdx.x * 128;

    Ah += blockIdx.z * sA + bm * K;  Al += blockIdx.z * sA + bm * K;
    Bh += blockIdx.z * sB + bn * K;  Bl += blockIdx.z * sB + bn * K;
    C  += blockIdx.z * sC;

    const int NS = K >> 6;

    float acc[4][4][4];
#pragma unroll
    for (int mi = 0; mi < 4; mi++)
#pragma unroll
        for (int ni = 0; ni < 4; ni++)
#pragma unroll
            for (int r = 0; r < 4; r++) acc[mi][ni][r] = 0.f;

    // per-thread load geometry: 4 chunks of 16B per tile per stage
    const int lr0 = tid >> 3;          // row base (0..31), +32 per j
    const int lkc = tid & 7;           // 16B chunk within 128B row

    auto load_stage = [&](int kb, int slot) {
        const uint32_t st = sb + slot * STAGE_BYTES;
        const long gk = (long)kb * 64;
#pragma unroll
        for (int j = 0; j < 4; j++) {
            const int row = lr0 + j * 32;
            const uint32_t so = swz((uint32_t)(row * 128 + lkc * 16));
            const long go = (long)row * K + gk + lkc * 8;
            cp16(st +          so, Ah + go);
            cp16(st + 16384 +  so, Al + go);
            cp16(st + 32768 +  so, Bh + go);
            cp16(st + 49152 +  so, Bl + go);
        }
    };

    auto compute_stage = [&](int slot) {
        const uint32_t st = sb + slot * STAGE_BYTES;
#pragma unroll
        for (int ks = 0; ks < 4; ks++) {
            uint32_t ahf[4][4], alf[4][4], bhf[4][2], blf[4][2];
#pragma unroll
            for (int mi = 0; mi < 4; mi++) {
                const int row = wm * 64 + mi * 16 + (lane & 15);
                const uint32_t off =
                    swz((uint32_t)(row * 128 + ks * 32 + ((lane >> 4) << 4)));
                ldsm4(ahf[mi], st + off);
                ldsm4(alf[mi], st + 16384 + off);
            }
#pragma unroll
            for (int ni = 0; ni < 4; ni++) {
                const int row = wn * 32 + ni * 8 + (lane & 7);
                const uint32_t off =
                    swz((uint32_t)(row * 128 + ks * 32 + (((lane >> 3) & 1) << 4)));
                ldsm2(bhf[ni], st + 32768 + off);
                ldsm2(blf[ni], st + 49152 + off);
            }
#pragma unroll
            for (int mi = 0; mi < 4; mi++)
#pragma unroll
                for (int ni = 0; ni < 4; ni++) {
                    mma16816(acc[mi][ni], ahf[mi], bhf[ni]);
                    mma16816(acc[mi][ni], ahf[mi], blf[ni]);
                    mma16816(acc[mi][ni], alf[mi], bhf[ni]);
                }
        }
    };

    load_stage(0, 0); CP_COMMIT();
    load_stage(1, 1); CP_COMMIT();

    for (int kb = 0; kb < NS; kb++) {
        if (kb + 2 < NS) load_stage(kb + 2, (kb + 2) % 3);
        CP_COMMIT();
        CP_WAIT(2);
        __syncthreads();
        compute_stage(kb % 3);
        __syncthreads();
    }

    // Epilogue: m16n8 f32 fragment: c0,c1 -> (row, col..col+1); c2,c3 -> row+8
#pragma unroll
    for (int mi = 0; mi < 4; mi++) {
        const long r0 = bm + wm * 64 + mi * 16 + (lane >> 2);
#pragma unroll
        for (int ni = 0; ni < 4; ni++) {
            const long c = bn + wn * 32 + ni * 8 + (lane & 3) * 2;
            float2 v0 = make_float2(acc[mi][ni][0], acc[mi][ni][1]);
            float2 v1 = make_float2(acc[mi][ni][2], acc[mi][ni][3]);
            *(float2*)(C + r0 * ldc + c)       = v0;
            *(float2*)(C + (r0 + 8) * ldc + c) = v1;
        }
    }
}

// ---------------------------------------------------------------------------
// Elementwise fp32 -> bf16 hi/lo split
// ---------------------------------------------------------------------------
__global__ void split_elem(const float* __restrict__ s,
                           __nv_bfloat16* __restrict__ h,
                           __nv_bfloat16* __restrict__ l, long n)
{
    long i = (long)blockIdx.x * blockDim.x + threadIdx.x;
    if (i >= n) return;
    float v = s[i];
    __nv_bfloat16 hi = __float2bfloat16(v);
    h[i] = hi;
    l[i] = __float2bfloat16(v - __bfloat162float(hi));
}

__global__ void split_v_kernel(const float* __restrict__ qkv2,
                               __nv_bfloat16* __restrict__ h,
                               __nv_bfloat16* __restrict__ l)
{
    const long per = (long)NC * NT;
    long i = (long)blockIdx.x * blockDim.x + threadIdx.x;
    if (i >= (long)NB * per) return;
    long b = i / per, r = i % per;
    float v = qkv2[b * ((long)N3C * NT) + 2L * NC * NT + r];
    __nv_bfloat16 hi = __float2bfloat16(v);
    h[i] = hi;
    l[i] = __float2bfloat16(v - __bfloat162float(hi));
}

// ---------------------------------------------------------------------------
// Transpose + optional per-t scale + bf16 split: src[C,T] -> dst[T,C]
// ---------------------------------------------------------------------------
__global__ void tsplit_kernel(const float* __restrict__ src, long bstride,
                              const float* __restrict__ inv, float scale,
                              __nv_bfloat16* __restrict__ dh,
                              __nv_bfloat16* __restrict__ dl)
{
    __shared__ float tile[32][33];
    const int b  = blockIdx.z;
    const int t0 = blockIdx.x * 32;
    const int c0 = blockIdx.y * 32;
    const int tx = threadIdx.x, ty = threadIdx.y;
    const float* s = src + (long)b * bstride;

#pragma unroll
    for (int i = 0; i < 4; i++)
        tile[ty * 4 + i][tx] = s[(long)(c0 + ty * 4 + i) * NT + t0 + tx];
    __syncthreads();

#pragma unroll
    for (int i = 0; i < 4; i++) {
        int tt = t0 + ty * 4 + i;
        int cc = c0 + tx;
        float sc = scale * (inv ? inv[(long)b * NT + tt] : 1.f);
        float v  = tile[tx][ty * 4 + i] * sc;
        __nv_bfloat16 hi = __float2bfloat16(v);
        long o = (long)b * NT * NC + (long)tt * NC + cc;
        dh[o] = hi;
        dl[o] = __float2bfloat16(v - __bfloat162float(hi));
    }
}

// ---------------------------------------------------------------------------
// Depthwise conv k=3 pad=1 over T
// ---------------------------------------------------------------------------
__global__ void dwconv3_kernel(const float* __restrict__ in,
                               const float* __restrict__ w,
                               float* __restrict__ out)
{
    const long total = (long)NB * N3C * NT;
    long idx = (long)blockIdx.x * blockDim.x + threadIdx.x;
    if (idx >= total) return;
    const int t  = (int)(idx % NT);
    const int ch = (int)((idx / NT) % N3C);
    const float w0 = w[ch * 3 + 0], w1 = w[ch * 3 + 1], w2 = w[ch * 3 + 2];
    const float xm = (t > 0)      ? in[idx - 1] : 0.f;
    const float x0 = in[idx];
    const float xp = (t < NT - 1) ? in[idx + 1] : 0.f;
    out[idx] = w0 * xm + w1 * x0 + w2 * xp;
}

// ---------------------------------------------------------------------------
// Per-(b,t) inverse L2 norms of q and k channels
// ---------------------------------------------------------------------------
__global__ void norms_kernel(const float* __restrict__ qkv2,
                             float* __restrict__ qinv, float* __restrict__ kinv)
{
    const int b = blockIdx.y;
    const int t = blockIdx.x * 128 + threadIdx.x;
    const float* base = qkv2 + (long)b * N3C * NT;
    float sq = 0.f, sk = 0.f;
    for (int c = 0; c < NC; c++) {
        float a = base[(long)c * NT + t];          sq += a * a;
        float d = base[(long)(NC + c) * NT + t];   sk += d * d;
    }
    qinv[(long)b * NT + t] = 1.f / fmaxf(sqrtf(sq), L2EPS);
    kinv[(long)b * NT + t] = 1.f / fmaxf(sqrtf(sk), L2EPS);
}

// ---------------------------------------------------------------------------
// Row softmax over T, fp32 scores in, bf16 hi/lo attn out
// ---------------------------------------------------------------------------
__inline__ __device__ float warpMax(float v) {
#pragma unroll
    for (int o = 16; o; o >>= 1) v = fmaxf(v, __shfl_xor_sync(0xffffffffu, v, o));
    return v;
}
__inline__ __device__ float warpSum(float v) {
#pragma unroll
    for (int o = 16; o; o >>= 1) v += __shfl_xor_sync(0xffffffffu, v, o);
    return v;
}

__global__ void softmax_split_kernel(const float* __restrict__ scores,
                                     __nv_bfloat16* __restrict__ ah,
                                     __nv_bfloat16* __restrict__ al)
{
    const long row = blockIdx.x;
    const float* p = scores + row * NT;
    const int tid  = threadIdx.x;
    const int lane = tid & 31;
    const int wid  = tid >> 5;
    __shared__ float red[8];

    float vals[8];
    float m = -1e30f;
#pragma unroll
    for (int i = 0; i < 8; i++) { vals[i] = p[tid + i * 256]; m = fmaxf(m, vals[i]); }
    m = warpMax(m);
    if (lane == 0) red[wid] = m;
    __syncthreads();
    if (wid == 0) {
        float v = (lane < 8) ? red[lane] : -1e30f;
        v = warpMax(v);
        if (lane == 0) red[0] = v;
    }
    __syncthreads();
    m = red[0];
    __syncthreads();

    float s = 0.f;
#pragma unroll
    for (int i = 0; i < 8; i++) { vals[i] = __expf(vals[i] - m); s += vals[i]; }
    s = warpSum(s);
    if (lane == 0) red[wid] = s;
    __syncthreads();
    if (wid == 0) {
        float v = (lane < 8) ? red[lane] : 0.f;
        v = warpSum(v);
        if (lane == 0) red[0] = v;
    }
    __syncthreads();
    const float inv = 1.f / red[0];
#pragma unroll
    for (int i = 0; i < 8; i++) {
        float v = vals[i] * inv;
        __nv_bfloat16 hi = __float2bfloat16(v);
        long o = row * NT + tid + i * 256;
        ah[o] = hi;
        al[o] = __float2bfloat16(v - __bfloat162float(hi));
    }
}

// ---------------------------------------------------------------------------
// Launch
// ---------------------------------------------------------------------------
extern "C" void kernel_launch(void* const* d_in, const int* in_sizes, int n_in,
                              void* d_out, int out_size)
{
    const float* x      = (const float*)d_in[0];
    const float* w_qkv  = (const float*)d_in[1];
    const float* w_dw   = (const float*)d_in[2];
    const float* w_proj = (const float*)d_in[3];
    float* out = (float*)d_out;

    cudaFuncSetAttribute(gemm_bf16x3, cudaFuncAttributeMaxDynamicSharedMemorySize, GEMM_SMEM);

    float *qkv, *qkv2, *scores, *outT, *qinv, *kinv;
    cudaGetSymbolAddress((void**)&qkv,    g_qkv);
    cudaGetSymbolAddress((void**)&qkv2,   g_qkv2);
    cudaGetSymbolAddress((void**)&scores, g_scores);
    cudaGetSymbolAddress((void**)&outT,   g_outT);
    cudaGetSymbolAddress((void**)&qinv,   g_qinv);
    cudaGetSymbolAddress((void**)&kinv,   g_kinv);

    __nv_bfloat16 *wqh, *wql, *wph, *wpl, *xth, *xtl, *qth, *qtl, *kth, *ktl,
                  *vh, *vl, *ath, *atl, *oth, *otl;
    cudaGetSymbolAddress((void**)&wqh, g_wq_h);  cudaGetSymbolAddress((void**)&wql, g_wq_l);
    cudaGetSymbolAddress((void**)&wph, g_wp_h);  cudaGetSymbolAddress((void**)&wpl, g_wp_l);
    cudaGetSymbolAddress((void**)&xth, g_xT_h);  cudaGetSymbolAddress((void**)&xtl, g_xT_l);
    cudaGetSymbolAddress((void**)&qth, g_qT_h);  cudaGetSymbolAddress((void**)&qtl, g_qT_l);
    cudaGetSymbolAddress((void**)&kth, g_kT_h);  cudaGetSymbolAddress((void**)&ktl, g_kT_l);
    cudaGetSymbolAddress((void**)&vh,  g_v_h);   cudaGetSymbolAddress((void**)&vl,  g_v_l);
    cudaGetSymbolAddress((void**)&ath, g_at_h);  cudaGetSymbolAddress((void**)&atl, g_at_l);
    cudaGetSymbolAddress((void**)&oth, g_oT_h);  cudaGetSymbolAddress((void**)&otl, g_oT_l);

    // weight splits
    split_elem<<<(unsigned)(((long)N3C * NC + 255) / 256), 256>>>(w_qkv, wqh, wql, (long)N3C * NC);
    split_elem<<<(unsigned)(((long)NC * NC + 255) / 256), 256>>>(w_proj, wph, wpl, (long)NC * NC);

    // xT split (transpose [C,T] -> [T,C])
    {
        dim3 grid(NT / 32, NC / 32, NB);
        tsplit_kernel<<<grid, dim3(32, 8)>>>(x, (long)NC * NT, nullptr, 1.f, xth, xtl);
    }

    // 1) qkv = W_qkv @ x : M=1536, N=2048, K=512
    {
        dim3 grid(NT / 128, N3C / 128, NB);
        gemm_bf16x3<<<grid, 256, GEMM_SMEM>>>(wqh, wql, xth, xtl, qkv,
            512, NT, 0L, (long)NT * NC, (long)N3C * NT);
    }

    // 2) depthwise conv
    {
        const long total = (long)NB * N3C * NT;
        dwconv3_kernel<<<(unsigned)((total + 255) / 256), 256>>>(qkv, w_dw, qkv2);
    }

    // 3) inverse norms for q, k
    norms_kernel<<<dim3(NT / 128, NB), 128>>>(qkv2, qinv, kinv);

    // 4) qT/kT transpose-split with fused normalization (+TEMP on q)
    {
        dim3 grid(NT / 32, NC / 32, NB);
        tsplit_kernel<<<grid, dim3(32, 8)>>>(qkv2, (long)N3C * NT, qinv, TEMP_INV, qth, qtl);
        tsplit_kernel<<<grid, dim3(32, 8)>>>(qkv2 + (long)NC * NT, (long)N3C * NT, kinv, 1.f, kth, ktl);
    }

    // 5) v split
    {
        const long total = (long)NB * NC * NT;
        split_v_kernel<<<(unsigned)((total + 255) / 256), 256>>>(qkv2, vh, vl);
    }

    // 6) scores = qT @ kT^T : M=N=2048, K=512
    {
        dim3 grid(NT / 128, NT / 128, NB);
        gemm_bf16x3<<<grid, 256, GEMM_SMEM>>>(qth, qtl, kth, ktl, scores,
            512, NT, (long)NT * NC, (long)NT * NC, (long)NT * NT);
    }

    // 7) softmax + bf16 split
    softmax_split_kernel<<<NB * NT, 256>>>(scores, ath, atl);

    // 8) outT = attn @ v^T : M=2048, N=512, K=2048
    {
        dim3 grid(NC / 128, NT / 128, NB);
        gemm_bf16x3<<<grid, 256, GEMM_SMEM>>>(ath, atl, vh, vl, outT,
            2048, NC, (long)NT * NT, (long)NC * NT, (long)NT * NC);
    }

    // 9) outT split
    {
        const long total = (long)NB * NT * NC;
        split_elem<<<(unsigned)((total + 255) / 256), 256>>>(outT, oth, otl, total);
    }

    // 10) final = W_proj @ outT^T : M=512, N=2048, K=512
    {
        dim3 grid(NT / 128, NC / 128, NB);
        gemm_bf16x3<<<grid, 256, GEMM_SMEM>>>(wph, wpl, oth, otl, out,
            512, NT, 0L, (long)NT * NC, (long)NC * NT);
    }
}

// round 9
// speedup vs baseline: 2.6560x; 1.0256x over previous
#include <cuda_runtime.h>
#include <cuda_bf16.h>
#include <math.h>
#include <stdint.h>

// Problem constants
#define NB 8
#define NC 512
#define NT 2048
#define N3C 1536
#define TEMP_INV (1.0f / 0.07f)
#define L2EPS 1e-12f

// ---------------------------------------------------------------------------
// Static scratch (no allocation allowed anywhere)
// ---------------------------------------------------------------------------
__device__ float g_qkv   [(size_t)NB * N3C * NT];
__device__ float g_qkv2  [(size_t)NB * 2 * NC * NT];   // q,k after dwconv
__device__ float g_scores[(size_t)NB * NT  * NT];
__device__ float g_qinv  [(size_t)NB * NT];
__device__ float g_kinv  [(size_t)NB * NT];

__device__ __nv_bfloat16 g_wq_h[(size_t)N3C * NC], g_wq_l[(size_t)N3C * NC];
__device__ __nv_bfloat16 g_wp_h[(size_t)NC  * NC], g_wp_l[(size_t)NC  * NC];
__device__ __nv_bfloat16 g_xT_h[(size_t)NB * NT * NC], g_xT_l[(size_t)NB * NT * NC];
__device__ __nv_bfloat16 g_qT_h[(size_t)NB * NT * NC], g_qT_l[(size_t)NB * NT * NC];
__device__ __nv_bfloat16 g_kT_h[(size_t)NB * NT * NC], g_kT_l[(size_t)NB * NT * NC];
__device__ __nv_bfloat16 g_v_h [(size_t)NB * NC * NT], g_v_l [(size_t)NB * NC * NT];
__device__ __nv_bfloat16 g_at_h[(size_t)NB * NT * NT], g_at_l[(size_t)NB * NT * NT];
__device__ __nv_bfloat16 g_oT_h[(size_t)NB * NT * NC], g_oT_l[(size_t)NB * NT * NC];

// ---------------------------------------------------------------------------
// PTX helpers (baseline sm_80+ only)
// ---------------------------------------------------------------------------
__device__ __forceinline__ uint32_t s2u(const void* p) {
    uint32_t a;
    asm("{ .reg .u64 t; cvta.to.shared.u64 t, %1; cvt.u32.u64 %0, t; }"
        : "=r"(a) : "l"(p));
    return a;
}

__device__ __forceinline__ void cp16(uint32_t s, const void* g) {
    asm volatile("cp.async.cg.shared.global [%0], [%1], 16;" :: "r"(s), "l"(g));
}
#define CP_COMMIT() asm volatile("cp.async.commit_group;" ::: "memory")
#define CP_WAIT(n)  asm volatile("cp.async.wait_group %0;" :: "n"(n) : "memory")

__device__ __forceinline__ void ldsm4(uint32_t* r, uint32_t a) {
    asm volatile("ldmatrix.sync.aligned.m8n8.x4.shared.b16 {%0,%1,%2,%3}, [%4];"
                 : "=r"(r[0]), "=r"(r[1]), "=r"(r[2]), "=r"(r[3]) : "r"(a));
}
__device__ __forceinline__ void ldsm2(uint32_t* r, uint32_t a) {
    asm volatile("ldmatrix.sync.aligned.m8n8.x2.shared.b16 {%0,%1}, [%2];"
                 : "=r"(r[0]), "=r"(r[1]) : "r"(a));
}

__device__ __forceinline__ void mma16816(float* c, const uint32_t* a, const uint32_t* b) {
    asm volatile(
        "mma.sync.aligned.m16n8k16.row.col.f32.bf16.bf16.f32 "
        "{%0,%1,%2,%3}, {%4,%5,%6,%7}, {%8,%9}, {%0,%1,%2,%3};"
        : "+f"(c[0]), "+f"(c[1]), "+f"(c[2]), "+f"(c[3])
        : "r"(a[0]), "r"(a[1]), "r"(a[2]), "r"(a[3]), "r"(b[0]), "r"(b[1]));
}

// 128-byte-row XOR swizzle
__device__ __forceinline__ uint32_t swz(uint32_t b) {
    return b ^ (((b >> 7) & 7) << 4);
}

// ---------------------------------------------------------------------------
// bf16x3 GEMM: C[M,N] = sum_k (Ah+Al)[m,k]*(Bh+Bl)[n,k], lo*lo dropped.
// A,B K-major (row stride = K). 128x128 CTA tile, BK=32, 3-stage cp.async.
// Tile packing: logical (row r, k) -> smem byte (r&63)*128 + (r>>6)*64 + k*2,
// then 128B swizzle. (r>>6) is warp-constant for all ldmatrix groups.
// 8 warps: wm = wid&1 (2 x 64 rows), wn = wid>>1 (4 x 32 cols).
// OUT=0: fp32 C. OUT=1: bf16 hi/lo split into Oh/Ol.
// ---------------------------------------------------------------------------
#define TILE_BYTES  8192           // 128x32 bf16
#define STAGE_BYTES 32768          // 4 tiles
#define NSTAGE 3
#define GEMM_SMEM (NSTAGE * STAGE_BYTES)   // 96 KB -> 2 CTAs/SM

template <int OUT>
__global__ __launch_bounds__(256, 2)
void gemm_bf16x3(const __nv_bfloat16* __restrict__ Ah, const __nv_bfloat16* __restrict__ Al,
                 const __nv_bfloat16* __restrict__ Bh, const __nv_bfloat16* __restrict__ Bl,
                 float* __restrict__ C,
                 __nv_bfloat16* __restrict__ Oh, __nv_bfloat16* __restrict__ Ol,
                 int K, int ldc, long sA, long sB, long sC)
{
    extern __shared__ __align__(1024) char smem[];
    const uint32_t sb = s2u(smem);
    const int tid  = threadIdx.x;
    const int lane = tid & 31;
    const int wid  = tid >> 5;
    const int wm   = wid & 1;
    const int wn   = wid >> 1;
    const long bm  = (long)blockIdx.y * 128;
    const long bn  = (long)blockIdx.x * 128;

    Ah += blockIdx.z * sA + bm * K;  Al += blockIdx.z * sA + bm * K;
    Bh += blockIdx.z * sB + bn * K;  Bl += blockIdx.z * sB + bn * K;

    const int NS = K >> 5;

    float acc[4][4][4];
#pragma unroll
    for (int mi = 0; mi < 4; mi++)
#pragma unroll
        for (int ni = 0; ni < 4; ni++)
#pragma unroll
            for (int r = 0; r < 4; r++) acc[mi][ni][r] = 0.f;

    auto load_stage = [&](int kb, int slot) {
        const uint32_t st = sb + slot * STAGE_BYTES;
        const long gk = (long)kb * 32;
#pragma unroll
        for (int j = 0; j < 2; j++) {
            const int c   = tid + j * 256;     // chunk id 0..511
            const int row = c >> 2;
            const int kc  = c & 3;
            const uint32_t so =
                swz((uint32_t)((row & 63) * 128 + (row >> 6) * 64 + kc * 16));
            const long go = (long)row * K + gk + kc * 8;
            cp16(st +          so, Ah + go);
            cp16(st +  8192 +  so, Al + go);
            cp16(st + 16384 +  so, Bh + go);
            cp16(st + 24576 +  so, Bl + go);
        }
    };

    auto compute_stage = [&](int slot) {
        const uint32_t st = sb + slot * STAGE_BYTES;
#pragma unroll
        for (int ks = 0; ks < 2; ks++) {
            uint32_t bhf[4][2], blf[4][2];
#pragma unroll
            for (int ni = 0; ni < 4; ni++) {
                const int n = wn * 32 + ni * 8 + (lane & 7);
                const uint32_t off = swz((uint32_t)(
                    (n & 63) * 128 + (n >> 6) * 64 + ks * 32 + (((lane >> 3) & 1) << 4)));
                ldsm2(bhf[ni], st + 16384 + off);
                ldsm2(blf[ni], st + 24576 + off);
            }
#pragma unroll
            for (int mi = 0; mi < 4; mi++) {
                uint32_t ahf[4], alf[4];
                const uint32_t off = swz((uint32_t)(
                    (mi * 16 + (lane & 15)) * 128 + wm * 64 + ks * 32 + ((lane >> 4) << 4)));
                ldsm4(ahf, st + off);
                ldsm4(alf, st + 8192 + off);
#pragma unroll
                for (int ni = 0; ni < 4; ni++) {
                    mma16816(acc[mi][ni], ahf, bhf[ni]);
                    mma16816(acc[mi][ni], ahf, blf[ni]);
                    mma16816(acc[mi][ni], alf, bhf[ni]);
                }
            }
        }
    };

    load_stage(0, 0); CP_COMMIT();
    load_stage(1, 1); CP_COMMIT();

    for (int kb = 0; kb < NS; kb++) {
        if (kb + 2 < NS) load_stage(kb + 2, (kb + 2) % 3);
        CP_COMMIT();
        CP_WAIT(2);
        __syncthreads();
        compute_stage(kb % 3);
        __syncthreads();
    }

    // Epilogue
    if (OUT == 0) {
        C += blockIdx.z * sC;
#pragma unroll
        for (int mi = 0; mi < 4; mi++) {
            const long r0 = bm + wm * 64 + mi * 16 + (lane >> 2);
#pragma unroll
            for (int ni = 0; ni < 4; ni++) {
                const long c = bn + wn * 32 + ni * 8 + (lane & 3) * 2;
                *(float2*)(C + r0 * ldc + c) =
                    make_float2(acc[mi][ni][0], acc[mi][ni][1]);
                *(float2*)(C + (r0 + 8) * ldc + c) =
                    make_float2(acc[mi][ni][2], acc[mi][ni][3]);
            }
        }
    } else {
        Oh += blockIdx.z * sC;  Ol += blockIdx.z * sC;
#pragma unroll
        for (int mi = 0; mi < 4; mi++) {
            const long r0 = bm + wm * 64 + mi * 16 + (lane >> 2);
#pragma unroll
            for (int ni = 0; ni < 4; ni++) {
                const long c = bn + wn * 32 + ni * 8 + (lane & 3) * 2;
#pragma unroll
                for (int p = 0; p < 2; p++) {
                    const long r = r0 + p * 8;
                    float vx = acc[mi][ni][2 * p], vy = acc[mi][ni][2 * p + 1];
                    __nv_bfloat16 hx = __float2bfloat16(vx);
                    __nv_bfloat16 hy = __float2bfloat16(vy);
                    __nv_bfloat16 lx = __float2bfloat16(vx - __bfloat162float(hx));
                    __nv_bfloat16 ly = __float2bfloat16(vy - __bfloat162float(hy));
                    *(__nv_bfloat162*)(Oh + r * ldc + c) = __nv_bfloat162(hx, hy);
                    *(__nv_bfloat162*)(Ol + r * ldc + c) = __nv_bfloat162(lx, ly);
                }
            }
        }
    }
}

// ---------------------------------------------------------------------------
// Elementwise fp32 -> bf16 hi/lo split
// ---------------------------------------------------------------------------
__global__ void split_elem(const float* __restrict__ s,
                           __nv_bfloat16* __restrict__ h,
                           __nv_bfloat16* __restrict__ l, long n)
{
    long i = (long)blockIdx.x * blockDim.x + threadIdx.x;
    if (i >= n) return;
    float v = s[i];
    __nv_bfloat16 hi = __float2bfloat16(v);
    h[i] = hi;
    l[i] = __float2bfloat16(v - __bfloat162float(hi));
}

// ---------------------------------------------------------------------------
// Transpose + optional per-t scale + bf16 split: src[C,T] -> dst[T,C]
// ---------------------------------------------------------------------------
__global__ void tsplit_kernel(const float* __restrict__ src, long bstride,
                              const float* __restrict__ inv, float scale,
                              __nv_bfloat16* __restrict__ dh,
                              __nv_bfloat16* __restrict__ dl)
{
    __shared__ float tile[32][33];
    const int b  = blockIdx.z;
    const int t0 = blockIdx.x * 32;
    const int c0 = blockIdx.y * 32;
    const int tx = threadIdx.x, ty = threadIdx.y;
    const float* s = src + (long)b * bstride;

#pragma unroll
    for (int i = 0; i < 4; i++)
        tile[ty * 4 + i][tx] = s[(long)(c0 + ty * 4 + i) * NT + t0 + tx];
    __syncthreads();

#pragma unroll
    for (int i = 0; i < 4; i++) {
        int tt = t0 + ty * 4 + i;
        int cc = c0 + tx;
        float sc = scale * (inv ? inv[(long)b * NT + tt] : 1.f);
        float v  = tile[tx][ty * 4 + i] * sc;
        __nv_bfloat16 hi = __float2bfloat16(v);
        long o = (long)b * NT * NC + (long)tt * NC + cc;
        dh[o] = hi;
        dl[o] = __float2bfloat16(v - __bfloat162float(hi));
    }
}

// ---------------------------------------------------------------------------
// Depthwise conv k=3 pad=1 over T; q,k -> fp32 qkv2; v -> bf16 hi/lo direct
// ---------------------------------------------------------------------------
__global__ void dwconv3_kernel(const float* __restrict__ in,
                               const float* __restrict__ w,
                               float* __restrict__ out_qk,
                               __nv_bfloat16* __restrict__ vh,
                               __nv_bfloat16* __restrict__ vl)
{
    const long total = (long)NB * N3C * NT;
    long idx = (long)blockIdx.x * blockDim.x + threadIdx.x;
    if (idx >= total) return;
    const int t  = (int)(idx % NT);
    const int ch = (int)((idx / NT) % N3C);
    const int b  = (int)(idx / ((long)N3C * NT));
    const float w0 = w[ch * 3 + 0], w1 = w[ch * 3 + 1], w2 = w[ch * 3 + 2];
    const float xm = (t > 0)      ? in[idx - 1] : 0.f;
    const float x0 = in[idx];
    const float xp = (t < NT - 1) ? in[idx + 1] : 0.f;
    const float val = w0 * xm + w1 * x0 + w2 * xp;

    if (ch < 2 * NC) {
        out_qk[(long)b * 2 * NC * NT + (long)ch * NT + t] = val;
    } else {
        long o = (long)b * NC * NT + (long)(ch - 2 * NC) * NT + t;
        __nv_bfloat16 hi = __float2bfloat16(val);
        vh[o] = hi;
        vl[o] = __float2bfloat16(val - __bfloat162float(hi));
    }
}

// ---------------------------------------------------------------------------
// Per-(b,t) inverse L2 norms of q and k channels (qkv2 = [2C,T] per batch)
// ---------------------------------------------------------------------------
__global__ void norms_kernel(const float* __restrict__ qkv2,
                             float* __restrict__ qinv, float* __restrict__ kinv)
{
    const int b = blockIdx.y;
    const int t = blockIdx.x * 128 + threadIdx.x;
    const float* base = qkv2 + (long)b * 2 * NC * NT;
    float sq = 0.f, sk = 0.f;
    for (int c = 0; c < NC; c++) {
        float a = base[(long)c * NT + t];          sq += a * a;
        float d = base[(long)(NC + c) * NT + t];   sk += d * d;
    }
    qinv[(long)b * NT + t] = 1.f / fmaxf(sqrtf(sq), L2EPS);
    kinv[(long)b * NT + t] = 1.f / fmaxf(sqrtf(sk), L2EPS);
}

// ---------------------------------------------------------------------------
// Row softmax over T, fp32 scores in, bf16 hi/lo attn out
// ---------------------------------------------------------------------------
__inline__ __device__ float warpMax(float v) {
#pragma unroll
    for (int o = 16; o; o >>= 1) v = fmaxf(v, __shfl_xor_sync(0xffffffffu, v, o));
    return v;
}
__inline__ __device__ float warpSum(float v) {
#pragma unroll
    for (int o = 16; o; o >>= 1) v += __shfl_xor_sync(0xffffffffu, v, o);
    return v;
}

__global__ void softmax_split_kernel(const float* __restrict__ scores,
                                     __nv_bfloat16* __restrict__ ah,
                                     __nv_bfloat16* __restrict__ al)
{
    const long row = blockIdx.x;
    const float* p = scores + row * NT;
    const int tid  = threadIdx.x;
    const int lane = tid & 31;
    const int wid  = tid >> 5;
    __shared__ float red[8];

    float vals[8];
    float m = -1e30f;
#pragma unroll
    for (int i = 0; i < 8; i++) { vals[i] = p[tid + i * 256]; m = fmaxf(m, vals[i]); }
    m = warpMax(m);
    if (lane == 0) red[wid] = m;
    __syncthreads();
    if (wid == 0) {
        float v = (lane < 8) ? red[lane] : -1e30f;
        v = warpMax(v);
        if (lane == 0) red[0] = v;
    }
    __syncthreads();
    m = red[0];
    __syncthreads();

    float s = 0.f;
#pragma unroll
    for (int i = 0; i < 8; i++) { vals[i] = __expf(vals[i] - m); s += vals[i]; }
    s = warpSum(s);
    if (lane == 0) red[wid] = s;
    __syncthreads();
    if (wid == 0) {
        float v = (lane < 8) ? red[lane] : 0.f;
        v = warpSum(v);
        if (lane == 0) red[0] = v;
    }
    __syncthreads();
    const float inv = 1.f / red[0];
#pragma unroll
    for (int i = 0; i < 8; i++) {
        float v = vals[i] * inv;
        __nv_bfloat16 hi = __float2bfloat16(v);
        long o = row * NT + tid + i * 256;
        ah[o] = hi;
        al[o] = __float2bfloat16(v - __bfloat162float(hi));
    }
}

// ---------------------------------------------------------------------------
// Launch
// ---------------------------------------------------------------------------
extern "C" void kernel_launch(void* const* d_in, const int* in_sizes, int n_in,
                              void* d_out, int out_size)
{
    const float* x      = (const float*)d_in[0];
    const float* w_qkv  = (const float*)d_in[1];
    const float* w_dw   = (const float*)d_in[2];
    const float* w_proj = (const float*)d_in[3];
    float* out = (float*)d_out;

    cudaFuncSetAttribute(gemm_bf16x3<0>, cudaFuncAttributeMaxDynamicSharedMemorySize, GEMM_SMEM);
    cudaFuncSetAttribute(gemm_bf16x3<1>, cudaFuncAttributeMaxDynamicSharedMemorySize, GEMM_SMEM);

    float *qkv, *qkv2, *scores, *qinv, *kinv;
    cudaGetSymbolAddress((void**)&qkv,    g_qkv);
    cudaGetSymbolAddress((void**)&qkv2,   g_qkv2);
    cudaGetSymbolAddress((void**)&scores, g_scores);
    cudaGetSymbolAddress((void**)&qinv,   g_qinv);
    cudaGetSymbolAddress((void**)&kinv,   g_kinv);

    __nv_bfloat16 *wqh, *wql, *wph, *wpl, *xth, *xtl, *qth, *qtl, *kth, *ktl,
                  *vh, *vl, *ath, *atl, *oth, *otl;
    cudaGetSymbolAddress((void**)&wqh, g_wq_h);  cudaGetSymbolAddress((void**)&wql, g_wq_l);
    cudaGetSymbolAddress((void**)&wph, g_wp_h);  cudaGetSymbolAddress((void**)&wpl, g_wp_l);
    cudaGetSymbolAddress((void**)&xth, g_xT_h);  cudaGetSymbolAddress((void**)&xtl, g_xT_l);
    cudaGetSymbolAddress((void**)&qth, g_qT_h);  cudaGetSymbolAddress((void**)&qtl, g_qT_l);
    cudaGetSymbolAddress((void**)&kth, g_kT_h);  cudaGetSymbolAddress((void**)&ktl, g_kT_l);
    cudaGetSymbolAddress((void**)&vh,  g_v_h);   cudaGetSymbolAddress((void**)&vl,  g_v_l);
    cudaGetSymbolAddress((void**)&ath, g_at_h);  cudaGetSymbolAddress((void**)&atl, g_at_l);
    cudaGetSymbolAddress((void**)&oth, g_oT_h);  cudaGetSymbolAddress((void**)&otl, g_oT_l);

    // weight splits
    split_elem<<<(unsigned)(((long)N3C * NC + 255) / 256), 256>>>(w_qkv, wqh, wql, (long)N3C * NC);
    split_elem<<<(unsigned)(((long)NC * NC + 255) / 256), 256>>>(w_proj, wph, wpl, (long)NC * NC);

    // xT split (transpose [C,T] -> [T,C])
    {
        dim3 grid(NT / 32, NC / 32, NB);
        tsplit_kernel<<<grid, dim3(32, 8)>>>(x, (long)NC * NT, nullptr, 1.f, xth, xtl);
    }

    // 1) qkv = W_qkv @ x : M=1536, N=2048, K=512 -> fp32
    {
        dim3 grid(NT / 128, N3C / 128, NB);
        gemm_bf16x3<0><<<grid, 256, GEMM_SMEM>>>(wqh, wql, xth, xtl, qkv, nullptr, nullptr,
            512, NT, 0L, (long)NT * NC, (long)N3C * NT);
    }

    // 2) depthwise conv (q,k -> qkv2 fp32; v -> vh/vl bf16 direct)
    {
        const long total = (long)NB * N3C * NT;
        dwconv3_kernel<<<(unsigned)((total + 255) / 256), 256>>>(qkv, w_dw, qkv2, vh, vl);
    }

    // 3) inverse norms for q, k
    norms_kernel<<<dim3(NT / 128, NB), 128>>>(qkv2, qinv, kinv);

    // 4) qT/kT transpose-split with fused normalization (+TEMP on q)
    {
        dim3 grid(NT / 32, NC / 32, NB);
        tsplit_kernel<<<grid, dim3(32, 8)>>>(qkv2, (long)2 * NC * NT, qinv, TEMP_INV, qth, qtl);
        tsplit_kernel<<<grid, dim3(32, 8)>>>(qkv2 + (long)NC * NT, (long)2 * NC * NT, kinv, 1.f, kth, ktl);
    }

    // 5) scores = qT @ kT^T : M=N=2048, K=512 -> fp32
    {
        dim3 grid(NT / 128, NT / 128, NB);
        gemm_bf16x3<0><<<grid, 256, GEMM_SMEM>>>(qth, qtl, kth, ktl, scores, nullptr, nullptr,
            512, NT, (long)NT * NC, (long)NT * NC, (long)NT * NT);
    }

    // 6) softmax + bf16 split
    softmax_split_kernel<<<NB * NT, 256>>>(scores, ath, atl);

    // 7) outT = attn @ v^T : M=2048, N=512, K=2048 -> bf16 hi/lo direct
    {
        dim3 grid(NC / 128, NT / 128, NB);
        gemm_bf16x3<1><<<grid, 256, GEMM_SMEM>>>(ath, atl, vh, vl, nullptr, oth, otl,
            2048, NC, (long)NT * NT, (long)NC * NT, (long)NT * NC);
    }

    // 8) final = W_proj @ outT^T : M=512, N=2048, K=512 -> fp32 d_out
    {
        dim3 grid(NT / 128, NC / 128, NB);
        gemm_bf16x3<0><<<grid, 256, GEMM_SMEM>>>(wph, wpl, oth, otl, out, nullptr, nullptr,
            512, NT, 0L, (long)NT * NC, (long)NC * NT);
    }
}

// round 10
// speedup vs baseline: 2.8245x; 1.0634x over previous
#include <cuda_runtime.h>
#include <cuda_bf16.h>
#include <math.h>
#include <stdint.h>

// Problem constants
#define NB 8
#define NC 512
#define NT 2048
#define N3C 1536
#define TEMP_INV (1.0f / 0.07f)
#define L2EPS 1e-12f

// ---------------------------------------------------------------------------
// Static scratch (no allocation allowed anywhere)
// ---------------------------------------------------------------------------
__device__ float g_qkv   [(size_t)NB * N3C * NT];
__device__ float g_qkv2  [(size_t)NB * 2 * NC * NT];   // q,k after dwconv
__device__ float g_scores[(size_t)NB * NT  * NT];
__device__ float g_qinv  [(size_t)NB * NT];
__device__ float g_kinv  [(size_t)NB * NT];

__device__ __nv_bfloat16 g_wq_h[(size_t)N3C * NC], g_wq_l[(size_t)N3C * NC];
__device__ __nv_bfloat16 g_wp_h[(size_t)NC  * NC], g_wp_l[(size_t)NC  * NC];
__device__ __nv_bfloat16 g_xT_h[(size_t)NB * NT * NC], g_xT_l[(size_t)NB * NT * NC];
__device__ __nv_bfloat16 g_qT_h[(size_t)NB * NT * NC], g_qT_l[(size_t)NB * NT * NC];
__device__ __nv_bfloat16 g_kT_h[(size_t)NB * NT * NC], g_kT_l[(size_t)NB * NT * NC];
__device__ __nv_bfloat16 g_v_h [(size_t)NB * NC * NT], g_v_l [(size_t)NB * NC * NT];
__device__ __nv_bfloat16 g_at_h[(size_t)NB * NT * NT], g_at_l[(size_t)NB * NT * NT];
__device__ __nv_bfloat16 g_oT_h[(size_t)NB * NT * NC], g_oT_l[(size_t)NB * NT * NC];

// ---------------------------------------------------------------------------
// PTX helpers (baseline sm_80+ only)
// ---------------------------------------------------------------------------
__device__ __forceinline__ uint32_t s2u(const void* p) {
    uint32_t a;
    asm("{ .reg .u64 t; cvta.to.shared.u64 t, %1; cvt.u32.u64 %0, t; }"
        : "=r"(a) : "l"(p));
    return a;
}

__device__ __forceinline__ void cp16(uint32_t s, const void* g) {
    asm volatile("cp.async.cg.shared.global [%0], [%1], 16;" :: "r"(s), "l"(g));
}
#define CP_COMMIT() asm volatile("cp.async.commit_group;" ::: "memory")
#define CP_WAIT(n)  asm volatile("cp.async.wait_group %0;" :: "n"(n) : "memory")

__device__ __forceinline__ void ldsm4(uint32_t* r, uint32_t a) {
    asm volatile("ldmatrix.sync.aligned.m8n8.x4.shared.b16 {%0,%1,%2,%3}, [%4];"
                 : "=r"(r[0]), "=r"(r[1]), "=r"(r[2]), "=r"(r[3]) : "r"(a));
}

__device__ __forceinline__ void mma16816(float* c, const uint32_t* a, const uint32_t* b) {
    asm volatile(
        "mma.sync.aligned.m16n8k16.row.col.f32.bf16.bf16.f32 "
        "{%0,%1,%2,%3}, {%4,%5,%6,%7}, {%8,%9}, {%0,%1,%2,%3};"
        : "+f"(c[0]), "+f"(c[1]), "+f"(c[2]), "+f"(c[3])
        : "r"(a[0]), "r"(a[1]), "r"(a[2]), "r"(a[3]), "r"(b[0]), "r"(b[1]));
}

// 128-byte-row XOR swizzle
__device__ __forceinline__ uint32_t swz(uint32_t b) {
    return b ^ (((b >> 7) & 7) << 4);
}

// ---------------------------------------------------------------------------
// bf16x3 GEMM: C[M,N] = sum_k (Ah+Al)[m,k]*(Bh+Bl)[n,k], lo*lo dropped.
// A,B K-major (row stride = K). 128x128 CTA tile, BK=32, 3-stage cp.async.
// Tile packing: logical (row r, k) -> smem byte (r&63)*128 + (r>>6)*64 + k*2,
// then 128B swizzle. One __syncthreads per stage; a cp.async group is
// committed every iteration (empty in tail) so wait_group(1) always proves
// group kb has fully landed before compute(kb).
// 8 warps: wm = wid&1 (2 x 64 rows), wn = wid>>1 (4 x 32 cols).
// OUT=0: fp32 C. OUT=1: bf16 hi/lo split into Oh/Ol.
// ---------------------------------------------------------------------------
#define STAGE_BYTES 32768          // 4 tiles (Ah,Al,Bh,Bl) x 128x32 bf16
#define NSTAGE 3
#define GEMM_SMEM (NSTAGE * STAGE_BYTES)   // 96 KB -> 2 CTAs/SM

template <int OUT>
__global__ __launch_bounds__(256, 2)
void gemm_bf16x3(const __nv_bfloat16* __restrict__ Ah, const __nv_bfloat16* __restrict__ Al,
                 const __nv_bfloat16* __restrict__ Bh, const __nv_bfloat16* __restrict__ Bl,
                 float* __restrict__ C,
                 __nv_bfloat16* __restrict__ Oh, __nv_bfloat16* __restrict__ Ol,
                 int K, int ldc, long sA, long sB, long sC)
{
    extern __shared__ __align__(1024) char smem[];
    const uint32_t sb = s2u(smem);
    const int tid  = threadIdx.x;
    const int lane = tid & 31;
    const int wid  = tid >> 5;
    const int wm   = wid & 1;
    const int wn   = wid >> 1;
    const long bm  = (long)blockIdx.y * 128;
    const long bn  = (long)blockIdx.x * 128;

    Ah += blockIdx.z * sA + bm * K;  Al += blockIdx.z * sA + bm * K;
    Bh += blockIdx.z * sB + bn * K;  Bl += blockIdx.z * sB + bn * K;

    const int NS = K >> 5;

    float acc[4][4][4];
#pragma unroll
    for (int mi = 0; mi < 4; mi++)
#pragma unroll
        for (int ni = 0; ni < 4; ni++)
#pragma unroll
            for (int r = 0; r < 4; r++) acc[mi][ni][r] = 0.f;

    auto load_stage = [&](int kb, int slot) {
        const uint32_t st = sb + slot * STAGE_BYTES;
        const long gk = (long)kb * 32;
#pragma unroll
        for (int j = 0; j < 2; j++) {
            const int c   = tid + j * 256;     // chunk id 0..511
            const int row = c >> 2;
            const int kc  = c & 3;
            const uint32_t so =
                swz((uint32_t)((row & 63) * 128 + (row >> 6) * 64 + kc * 16));
            const long go = (long)row * K + gk + kc * 8;
            cp16(st +          so, Ah + go);
            cp16(st +  8192 +  so, Al + go);
            cp16(st + 16384 +  so, Bh + go);
            cp16(st + 24576 +  so, Bl + go);
        }
    };

    // B ldsm4 lane address: covers 2 n8 groups x 2 k-halves in one op.
    // group g = lane>>3, l = lane&7: n = base + (g>>1)*8 + l, kbyte += (g&1)*16
    auto b_addr = [&](uint32_t st, int ks, int nipair) -> uint32_t {
        const int g = lane >> 3, l = lane & 7;
        const int n = wn * 32 + nipair * 16 + (g >> 1) * 8 + l;
        const uint32_t kbyte = (uint32_t)(ks * 32 + (g & 1) * 16);
        return st + swz((uint32_t)((n & 63) * 128 + (n >> 6) * 64) + kbyte);
    };

    auto compute_stage = [&](int slot) {
        const uint32_t st = sb + slot * STAGE_BYTES;
#pragma unroll
        for (int ks = 0; ks < 2; ks++) {
            uint32_t bhf[2][4], blf[2][4];   // [nipair][4 regs = 2 ni x 2]
#pragma unroll
            for (int np = 0; np < 2; np++) {
                const uint32_t ba = b_addr(st, ks, np);
                ldsm4(bhf[np], 16384 + ba);
                ldsm4(blf[np],  24576 + ba);
            }
#pragma unroll
            for (int mi = 0; mi < 4; mi++) {
                uint32_t ahf[4], alf[4];
                const uint32_t off = swz((uint32_t)(
                    (mi * 16 + (lane & 15)) * 128 + wm * 64 + ks * 32 + ((lane >> 4) << 4)));
                ldsm4(ahf, st + off);
                ldsm4(alf, st + 8192 + off);
#pragma unroll
                for (int ni = 0; ni < 4; ni++) {
                    const uint32_t* bh = &bhf[ni >> 1][(ni & 1) * 2];
                    const uint32_t* bl = &blf[ni >> 1][(ni & 1) * 2];
                    mma16816(acc[mi][ni], ahf, bh);
                    mma16816(acc[mi][ni], ahf, bl);
                    mma16816(acc[mi][ni], alf, bh);
                }
            }
        }
    };

    load_stage(0, 0); CP_COMMIT();
    load_stage(1, 1); CP_COMMIT();

    for (int kb = 0; kb < NS; kb++) {
        CP_WAIT(1);            // group kb fully landed (exactly 2 outstanding)
        __syncthreads();       // all warps done with compute(kb-1) -> slot free
        if (kb + 2 < NS) load_stage(kb + 2, (kb + 2) % 3);
        CP_COMMIT();           // commit every iter (possibly empty) for uniform accounting
        compute_stage(kb % 3);
    }

    // Epilogue
    if (OUT == 0) {
        C += blockIdx.z * sC;
#pragma unroll
        for (int mi = 0; mi < 4; mi++) {
            const long r0 = bm + wm * 64 + mi * 16 + (lane >> 2);
#pragma unroll
            for (int ni = 0; ni < 4; ni++) {
                const long c = bn + wn * 32 + ni * 8 + (lane & 3) * 2;
                *(float2*)(C + r0 * ldc + c) =
                    make_float2(acc[mi][ni][0], acc[mi][ni][1]);
                *(float2*)(C + (r0 + 8) * ldc + c) =
                    make_float2(acc[mi][ni][2], acc[mi][ni][3]);
            }
        }
    } else {
        Oh += blockIdx.z * sC;  Ol += blockIdx.z * sC;
#pragma unroll
        for (int mi = 0; mi < 4; mi++) {
            const long r0 = bm + wm * 64 + mi * 16 + (lane >> 2);
#pragma unroll
            for (int ni = 0; ni < 4; ni++) {
                const long c = bn + wn * 32 + ni * 8 + (lane & 3) * 2;
#pragma unroll
                for (int p = 0; p < 2; p++) {
                    const long r = r0 + p * 8;
                    float vx = acc[mi][ni][2 * p], vy = acc[mi][ni][2 * p + 1];
                    __nv_bfloat16 hx = __float2bfloat16(vx);
                    __nv_bfloat16 hy = __float2bfloat16(vy);
                    __nv_bfloat16 lx = __float2bfloat16(vx - __bfloat162float(hx));
                    __nv_bfloat16 ly = __float2bfloat16(vy - __bfloat162float(hy));
                    *(__nv_bfloat162*)(Oh + r * ldc + c) = __nv_bfloat162(hx, hy);
                    *(__nv_bfloat162*)(Ol + r * ldc + c) = __nv_bfloat162(lx, ly);
                }
            }
        }
    }
}

// ---------------------------------------------------------------------------
// Elementwise fp32 -> bf16 hi/lo split
// ---------------------------------------------------------------------------
__global__ void split_elem(const float* __restrict__ s,
                           __nv_bfloat16* __restrict__ h,
                           __nv_bfloat16* __restrict__ l, long n)
{
    long i = (long)blockIdx.x * blockDim.x + threadIdx.x;
    if (i >= n) return;
    float v = s[i];
    __nv_bfloat16 hi = __float2bfloat16(v);
    h[i] = hi;
    l[i] = __float2bfloat16(v - __bfloat162float(hi));
}

// ---------------------------------------------------------------------------
// Transpose + optional per-t scale + bf16 split: src[C,T] -> dst[T,C]
// ---------------------------------------------------------------------------
__global__ void tsplit_kernel(const float* __restrict__ src, long bstride,
                              const float* __restrict__ inv, float scale,
                              __nv_bfloat16* __restrict__ dh,
                              __nv_bfloat16* __restrict__ dl)
{
    __shared__ float tile[32][33];
    const int b  = blockIdx.z;
    const int t0 = blockIdx.x * 32;
    const int c0 = blockIdx.y * 32;
    const int tx = threadIdx.x, ty = threadIdx.y;
    const float* s = src + (long)b * bstride;

#pragma unroll
    for (int i = 0; i < 4; i++)
        tile[ty * 4 + i][tx] = s[(long)(c0 + ty * 4 + i) * NT + t0 + tx];
    __syncthreads();

#pragma unroll
    for (int i = 0; i < 4; i++) {
        int tt = t0 + ty * 4 + i;
        int cc = c0 + tx;
        float sc = scale * (inv ? inv[(long)b * NT + tt] : 1.f);
        float v  = tile[tx][ty * 4 + i] * sc;
        __nv_bfloat16 hi = __float2bfloat16(v);
        long o = (long)b * NT * NC + (long)tt * NC + cc;
        dh[o] = hi;
        dl[o] = __float2bfloat16(v - __bfloat162float(hi));
    }
}

// ---------------------------------------------------------------------------
// Depthwise conv k=3 pad=1 over T; q,k -> fp32 qkv2; v -> bf16 hi/lo direct
// ---------------------------------------------------------------------------
__global__ void dwconv3_kernel(const float* __restrict__ in,
                               const float* __restrict__ w,
                               float* __restrict__ out_qk,
                               __nv_bfloat16* __restrict__ vh,
                               __nv_bfloat16* __restrict__ vl)
{
    const long total = (long)NB * N3C * NT;
    long idx = (long)blockIdx.x * blockDim.x + threadIdx.x;
    if (idx >= total) return;
    const int t  = (int)(idx % NT);
    const int ch = (int)((idx / NT) % N3C);
    const int b  = (int)(idx / ((long)N3C * NT));
    const float w0 = w[ch * 3 + 0], w1 = w[ch * 3 + 1], w2 = w[ch * 3 + 2];
    const float xm = (t > 0)      ? in[idx - 1] : 0.f;
    const float x0 = in[idx];
    const float xp = (t < NT - 1) ? in[idx + 1] : 0.f;
    const float val = w0 * xm + w1 * x0 + w2 * xp;

    if (ch < 2 * NC) {
        out_qk[(long)b * 2 * NC * NT + (long)ch * NT + t] = val;
    } else {
        long o = (long)b * NC * NT + (long)(ch - 2 * NC) * NT + t;
        __nv_bfloat16 hi = __float2bfloat16(val);
        vh[o] = hi;
        vl[o] = __float2bfloat16(val - __bfloat162float(hi));
    }
}

// ---------------------------------------------------------------------------
// Per-(b,t) inverse L2 norms of q and k channels (qkv2 = [2C,T] per batch)
// ---------------------------------------------------------------------------
__global__ void norms_kernel(const float* __restrict__ qkv2,
                             float* __restrict__ qinv, float* __restrict__ kinv)
{
    const int b = blockIdx.y;
    const int t = blockIdx.x * 128 + threadIdx.x;
    const float* base = qkv2 + (long)b * 2 * NC * NT;
    float sq = 0.f, sk = 0.f;
    for (int c = 0; c < NC; c++) {
        float a = base[(long)c * NT + t];          sq += a * a;
        float d = base[(long)(NC + c) * NT + t];   sk += d * d;
    }
    qinv[(long)b * NT + t] = 1.f / fmaxf(sqrtf(sq), L2EPS);
    kinv[(long)b * NT + t] = 1.f / fmaxf(sqrtf(sk), L2EPS);
}

// ---------------------------------------------------------------------------
// Row softmax over T, fp32 scores in, bf16 hi/lo attn out
// ---------------------------------------------------------------------------
__inline__ __device__ float warpMax(float v) {
#pragma unroll
    for (int o = 16; o; o >>= 1) v = fmaxf(v, __shfl_xor_sync(0xffffffffu, v, o));
    return v;
}
__inline__ __device__ float warpSum(float v) {
#pragma unroll
    for (int o = 16; o; o >>= 1) v += __shfl_xor_sync(0xffffffffu, v, o);
    return v;
}

__global__ void softmax_split_kernel(const float* __restrict__ scores,
                                     __nv_bfloat16* __restrict__ ah,
                                     __nv_bfloat16* __restrict__ al)
{
    const long row = blockIdx.x;
    const float* p = scores + row * NT;
    const int tid  = threadIdx.x;
    const int lane = tid & 31;
    const int wid  = tid >> 5;
    __shared__ float red[8];

    float vals[8];
    float m = -1e30f;
#pragma unroll
    for (int i = 0; i < 8; i++) { vals[i] = p[tid + i * 256]; m = fmaxf(m, vals[i]); }
    m = warpMax(m);
    if (lane == 0) red[wid] = m;
    __syncthreads();
    if (wid == 0) {
        float v = (lane < 8) ? red[lane] : -1e30f;
        v = warpMax(v);
        if (lane == 0) red[0] = v;
    }
    __syncthreads();
    m = red[0];
    __syncthreads();

    float s = 0.f;
#pragma unroll
    for (int i = 0; i < 8; i++) { vals[i] = __expf(vals[i] - m); s += vals[i]; }
    s = warpSum(s);
    if (lane == 0) red[wid] = s;
    __syncthreads();
    if (wid == 0) {
        float v = (lane < 8) ? red[lane] : 0.f;
        v = warpSum(v);
        if (lane == 0) red[0] = v;
    }
    __syncthreads();
    const float inv = 1.f / red[0];
#pragma unroll
    for (int i = 0; i < 8; i++) {
        float v = vals[i] * inv;
        __nv_bfloat16 hi = __float2bfloat16(v);
        long o = row * NT + tid + i * 256;
        ah[o] = hi;
        al[o] = __float2bfloat16(v - __bfloat162float(hi));
    }
}

// ---------------------------------------------------------------------------
// Launch
// ---------------------------------------------------------------------------
extern "C" void kernel_launch(void* const* d_in, const int* in_sizes, int n_in,
                              void* d_out, int out_size)
{
    const float* x      = (const float*)d_in[0];
    const float* w_qkv  = (const float*)d_in[1];
    const float* w_dw   = (const float*)d_in[2];
    const float* w_proj = (const float*)d_in[3];
    float* out = (float*)d_out;

    cudaFuncSetAttribute(gemm_bf16x3<0>, cudaFuncAttributeMaxDynamicSharedMemorySize, GEMM_SMEM);
    cudaFuncSetAttribute(gemm_bf16x3<1>, cudaFuncAttributeMaxDynamicSharedMemorySize, GEMM_SMEM);

    float *qkv, *qkv2, *scores, *qinv, *kinv;
    cudaGetSymbolAddress((void**)&qkv,    g_qkv);
    cudaGetSymbolAddress((void**)&qkv2,   g_qkv2);
    cudaGetSymbolAddress((void**)&scores, g_scores);
    cudaGetSymbolAddress((void**)&qinv,   g_qinv);
    cudaGetSymbolAddress((void**)&kinv,   g_kinv);

    __nv_bfloat16 *wqh, *wql, *wph, *wpl, *xth, *xtl, *qth, *qtl, *kth, *ktl,
                  *vh, *vl, *ath, *atl, *oth, *otl;
    cudaGetSymbolAddress((void**)&wqh, g_wq_h);  cudaGetSymbolAddress((void**)&wql, g_wq_l);
    cudaGetSymbolAddress((void**)&wph, g_wp_h);  cudaGetSymbolAddress((void**)&wpl, g_wp_l);
    cudaGetSymbolAddress((void**)&xth, g_xT_h);  cudaGetSymbolAddress((void**)&xtl, g_xT_l);
    cudaGetSymbolAddress((void**)&qth, g_qT_h);  cudaGetSymbolAddress((void**)&qtl, g_qT_l);
    cudaGetSymbolAddress((void**)&kth, g_kT_h);  cudaGetSymbolAddress((void**)&ktl, g_kT_l);
    cudaGetSymbolAddress((void**)&vh,  g_v_h);   cudaGetSymbolAddress((void**)&vl,  g_v_l);
    cudaGetSymbolAddress((void**)&ath, g_at_h);  cudaGetSymbolAddress((void**)&atl, g_at_l);
    cudaGetSymbolAddress((void**)&oth, g_oT_h);  cudaGetSymbolAddress((void**)&otl, g_oT_l);

    // weight splits
    split_elem<<<(unsigned)(((long)N3C * NC + 255) / 256), 256>>>(w_qkv, wqh, wql, (long)N3C * NC);
    split_elem<<<(unsigned)(((long)NC * NC + 255) / 256), 256>>>(w_proj, wph, wpl, (long)NC * NC);

    // xT split (transpose [C,T] -> [T,C])
    {
        dim3 grid(NT / 32, NC / 32, NB);
        tsplit_kernel<<<grid, dim3(32, 8)>>>(x, (long)NC * NT, nullptr, 1.f, xth, xtl);
    }

    // 1) qkv = W_qkv @ x : M=1536, N=2048, K=512 -> fp32
    {
        dim3 grid(NT / 128, N3C / 128, NB);
        gemm_bf16x3<0><<<grid, 256, GEMM_SMEM>>>(wqh, wql, xth, xtl, qkv, nullptr, nullptr,
            512, NT, 0L, (long)NT * NC, (long)N3C * NT);
    }

    // 2) depthwise conv (q,k -> qkv2 fp32; v -> vh/vl bf16 direct)
    {
        const long total = (long)NB * N3C * NT;
        dwconv3_kernel<<<(unsigned)((total + 255) / 256), 256>>>(qkv, w_dw, qkv2, vh, vl);
    }

    // 3) inverse norms for q, k
    norms_kernel<<<dim3(NT / 128, NB), 128>>>(qkv2, qinv, kinv);

    // 4) qT/kT transpose-split with fused normalization (+TEMP on q)
    {
        dim3 grid(NT / 32, NC / 32, NB);
        tsplit_kernel<<<grid, dim3(32, 8)>>>(qkv2, (long)2 * NC * NT, qinv, TEMP_INV, qth, qtl);
        tsplit_kernel<<<grid, dim3(32, 8)>>>(qkv2 + (long)NC * NT, (long)2 * NC * NT, kinv, 1.f, kth, ktl);
    }

    // 5) scores = qT @ kT^T : M=N=2048, K=512 -> fp32
    {
        dim3 grid(NT / 128, NT / 128, NB);
        gemm_bf16x3<0><<<grid, 256, GEMM_SMEM>>>(qth, qtl, kth, ktl, scores, nullptr, nullptr,
            512, NT, (long)NT * NC, (long)NT * NC, (long)NT * NT);
    }

    // 6) softmax + bf16 split
    softmax_split_kernel<<<NB * NT, 256>>>(scores, ath, atl);

    // 7) outT = attn @ v^T : M=2048, N=512, K=2048 -> bf16 hi/lo direct
    {
        dim3 grid(NC / 128, NT / 128, NB);
        gemm_bf16x3<1><<<grid, 256, GEMM_SMEM>>>(ath, atl, vh, vl, nullptr, oth, otl,
            2048, NC, (long)NT * NT, (long)NC * NT, (long)NT * NC);
    }

    // 8) final = W_proj @ outT^T : M=512, N=2048, K=512 -> fp32 d_out
    {
        dim3 grid(NT / 128, NC / 128, NB);
        gemm_bf16x3<0><<<grid, 256, GEMM_SMEM>>>(wph, wpl, oth, otl, out, nullptr, nullptr,
            512, NT, 0L, (long)NT * NC, (long)NC * NT);
    }
}

// round 11
// speedup vs baseline: 2.8589x; 1.0122x over previous
#include <cuda_runtime.h>
#include <cuda_bf16.h>
#include <math.h>
#include <stdint.h>

// Problem constants
#define NB 8
#define NC 512
#define NT 2048
#define N3C 1536
#define TEMP_INV (1.0f / 0.07f)
#define L2EPS 1e-12f

// ---------------------------------------------------------------------------
// Static scratch (no allocation allowed anywhere)
// ---------------------------------------------------------------------------
__device__ float g_qkv   [(size_t)NB * N3C * NT];
__device__ float g_qkv2  [(size_t)NB * 2 * NC * NT];   // q,k after dwconv
__device__ float g_scores[(size_t)NB * NT  * NT];
__device__ float g_qinv  [(size_t)NB * NT];
__device__ float g_kinv  [(size_t)NB * NT];

__device__ __nv_bfloat16 g_wq_h[(size_t)N3C * NC], g_wq_l[(size_t)N3C * NC];
__device__ __nv_bfloat16 g_wp_h[(size_t)NC  * NC], g_wp_l[(size_t)NC  * NC];
__device__ __nv_bfloat16 g_xT_h[(size_t)NB * NT * NC], g_xT_l[(size_t)NB * NT * NC];
__device__ __nv_bfloat16 g_qT_h[(size_t)NB * NT * NC], g_qT_l[(size_t)NB * NT * NC];
__device__ __nv_bfloat16 g_kT_h[(size_t)NB * NT * NC], g_kT_l[(size_t)NB * NT * NC];
__device__ __nv_bfloat16 g_v_h [(size_t)NB * NC * NT], g_v_l [(size_t)NB * NC * NT];
__device__ __nv_bfloat16 g_at_h[(size_t)NB * NT * NT], g_at_l[(size_t)NB * NT * NT];
__device__ __nv_bfloat16 g_oT_h[(size_t)NB * NT * NC], g_oT_l[(size_t)NB * NT * NC];

// ---------------------------------------------------------------------------
// PTX helpers (baseline sm_80+ only)
// ---------------------------------------------------------------------------
__device__ __forceinline__ uint32_t s2u(const void* p) {
    uint32_t a;
    asm("{ .reg .u64 t; cvta.to.shared.u64 t, %1; cvt.u32.u64 %0, t; }"
        : "=r"(a) : "l"(p));
    return a;
}

__device__ __forceinline__ void cp16(uint32_t s, const void* g) {
    asm volatile("cp.async.cg.shared.global [%0], [%1], 16;" :: "r"(s), "l"(g));
}
#define CP_COMMIT() asm volatile("cp.async.commit_group;" ::: "memory")
#define CP_WAIT(n)  asm volatile("cp.async.wait_group %0;" :: "n"(n) : "memory")

__device__ __forceinline__ void ldsm4(uint32_t* r, uint32_t a) {
    asm volatile("ldmatrix.sync.aligned.m8n8.x4.shared.b16 {%0,%1,%2,%3}, [%4];"
                 : "=r"(r[0]), "=r"(r[1]), "=r"(r[2]), "=r"(r[3]) : "r"(a));
}

__device__ __forceinline__ void mma16816(float* c, const uint32_t* a, const uint32_t* b) {
    asm volatile(
        "mma.sync.aligned.m16n8k16.row.col.f32.bf16.bf16.f32 "
        "{%0,%1,%2,%3}, {%4,%5,%6,%7}, {%8,%9}, {%0,%1,%2,%3};"
        : "+f"(c[0]), "+f"(c[1]), "+f"(c[2]), "+f"(c[3])
        : "r"(a[0]), "r"(a[1]), "r"(a[2]), "r"(a[3]), "r"(b[0]), "r"(b[1]));
}

// 128-byte-row XOR swizzle
__device__ __forceinline__ uint32_t swz(uint32_t b) {
    return b ^ (((b >> 7) & 7) << 4);
}

// pack two floats -> 2 bf16 in one u32
__device__ __forceinline__ uint32_t pack_hi2(float a, float b) {
    __nv_bfloat162 h = __floats2bfloat162_rn(a, b);
    return *(uint32_t*)&h;
}
__device__ __forceinline__ void split4(const float* v, uint2& hi, uint2& lo) {
    __nv_bfloat16 h0 = __float2bfloat16(v[0]);
    __nv_bfloat16 h1 = __float2bfloat16(v[1]);
    __nv_bfloat16 h2 = __float2bfloat16(v[2]);
    __nv_bfloat16 h3 = __float2bfloat16(v[3]);
    __nv_bfloat162 a = __nv_bfloat162(h0, h1), b = __nv_bfloat162(h2, h3);
    hi.x = *(uint32_t*)&a;  hi.y = *(uint32_t*)&b;
    __nv_bfloat162 c = __nv_bfloat162(__float2bfloat16(v[0] - __bfloat162float(h0)),
                                      __float2bfloat16(v[1] - __bfloat162float(h1)));
    __nv_bfloat162 d = __nv_bfloat162(__float2bfloat16(v[2] - __bfloat162float(h2)),
                                      __float2bfloat16(v[3] - __bfloat162float(h3)));
    lo.x = *(uint32_t*)&c;  lo.y = *(uint32_t*)&d;
}

// ---------------------------------------------------------------------------
// bf16x3 GEMM (unchanged from R10): C = sum (Ah+Al)(Bh+Bl), lo*lo dropped.
// ---------------------------------------------------------------------------
#define STAGE_BYTES 32768
#define NSTAGE 3
#define GEMM_SMEM (NSTAGE * STAGE_BYTES)   // 96 KB -> 2 CTAs/SM

template <int OUT>
__global__ __launch_bounds__(256, 2)
void gemm_bf16x3(const __nv_bfloat16* __restrict__ Ah, const __nv_bfloat16* __restrict__ Al,
                 const __nv_bfloat16* __restrict__ Bh, const __nv_bfloat16* __restrict__ Bl,
                 float* __restrict__ C,
                 __nv_bfloat16* __restrict__ Oh, __nv_bfloat16* __restrict__ Ol,
                 int K, int ldc, long sA, long sB, long sC)
{
    extern __shared__ __align__(1024) char smem[];
    const uint32_t sb = s2u(smem);
    const int tid  = threadIdx.x;
    const int lane = tid & 31;
    const int wid  = tid >> 5;
    const int wm   = wid & 1;
    const int wn   = wid >> 1;
    const long bm  = (long)blockIdx.y * 128;
    const long bn  = (long)blockIdx.x * 128;

    Ah += blockIdx.z * sA + bm * K;  Al += blockIdx.z * sA + bm * K;
    Bh += blockIdx.z * sB + bn * K;  Bl += blockIdx.z * sB + bn * K;

    const int NS = K >> 5;

    float acc[4][4][4];
#pragma unroll
    for (int mi = 0; mi < 4; mi++)
#pragma unroll
        for (int ni = 0; ni < 4; ni++)
#pragma unroll
            for (int r = 0; r < 4; r++) acc[mi][ni][r] = 0.f;

    auto load_stage = [&](int kb, int slot) {
        const uint32_t st = sb + slot * STAGE_BYTES;
        const long gk = (long)kb * 32;
#pragma unroll
        for (int j = 0; j < 2; j++) {
            const int c   = tid + j * 256;
            const int row = c >> 2;
            const int kc  = c & 3;
            const uint32_t so =
                swz((uint32_t)((row & 63) * 128 + (row >> 6) * 64 + kc * 16));
            const long go = (long)row * K + gk + kc * 8;
            cp16(st +          so, Ah + go);
            cp16(st +  8192 +  so, Al + go);
            cp16(st + 16384 +  so, Bh + go);
            cp16(st + 24576 +  so, Bl + go);
        }
    };

    auto b_addr = [&](uint32_t st, int ks, int nipair) -> uint32_t {
        const int g = lane >> 3, l = lane & 7;
        const int n = wn * 32 + nipair * 16 + (g >> 1) * 8 + l;
        const uint32_t kbyte = (uint32_t)(ks * 32 + (g & 1) * 16);
        return st + swz((uint32_t)((n & 63) * 128 + (n >> 6) * 64) + kbyte);
    };

    auto compute_stage = [&](int slot) {
        const uint32_t st = sb + slot * STAGE_BYTES;
#pragma unroll
        for (int ks = 0; ks < 2; ks++) {
            uint32_t bhf[2][4], blf[2][4];
#pragma unroll
            for (int np = 0; np < 2; np++) {
                const uint32_t ba = b_addr(st, ks, np);
                ldsm4(bhf[np], 16384 + ba);
                ldsm4(blf[np],  24576 + ba);
            }
#pragma unroll
            for (int mi = 0; mi < 4; mi++) {
                uint32_t ahf[4], alf[4];
                const uint32_t off = swz((uint32_t)(
                    (mi * 16 + (lane & 15)) * 128 + wm * 64 + ks * 32 + ((lane >> 4) << 4)));
                ldsm4(ahf, st + off);
                ldsm4(alf, st + 8192 + off);
#pragma unroll
                for (int ni = 0; ni < 4; ni++) {
                    const uint32_t* bh = &bhf[ni >> 1][(ni & 1) * 2];
                    const uint32_t* bl = &blf[ni >> 1][(ni & 1) * 2];
                    mma16816(acc[mi][ni], ahf, bh);
                    mma16816(acc[mi][ni], ahf, bl);
                    mma16816(acc[mi][ni], alf, bh);
                }
            }
        }
    };

    load_stage(0, 0); CP_COMMIT();
    load_stage(1, 1); CP_COMMIT();

    for (int kb = 0; kb < NS; kb++) {
        CP_WAIT(1);
        __syncthreads();
        if (kb + 2 < NS) load_stage(kb + 2, (kb + 2) % 3);
        CP_COMMIT();
        compute_stage(kb % 3);
    }

    if (OUT == 0) {
        C += blockIdx.z * sC;
#pragma unroll
        for (int mi = 0; mi < 4; mi++) {
            const long r0 = bm + wm * 64 + mi * 16 + (lane >> 2);
#pragma unroll
            for (int ni = 0; ni < 4; ni++) {
                const long c = bn + wn * 32 + ni * 8 + (lane & 3) * 2;
                *(float2*)(C + r0 * ldc + c) =
                    make_float2(acc[mi][ni][0], acc[mi][ni][1]);
                *(float2*)(C + (r0 + 8) * ldc + c) =
                    make_float2(acc[mi][ni][2], acc[mi][ni][3]);
            }
        }
    } else {
        Oh += blockIdx.z * sC;  Ol += blockIdx.z * sC;
#pragma unroll
        for (int mi = 0; mi < 4; mi++) {
            const long r0 = bm + wm * 64 + mi * 16 + (lane >> 2);
#pragma unroll
            for (int ni = 0; ni < 4; ni++) {
                const long c = bn + wn * 32 + ni * 8 + (lane & 3) * 2;
#pragma unroll
                for (int p = 0; p < 2; p++) {
                    const long r = r0 + p * 8;
                    float vx = acc[mi][ni][2 * p], vy = acc[mi][ni][2 * p + 1];
                    __nv_bfloat16 hx = __float2bfloat16(vx);
                    __nv_bfloat16 hy = __float2bfloat16(vy);
                    __nv_bfloat16 lx = __float2bfloat16(vx - __bfloat162float(hx));
                    __nv_bfloat16 ly = __float2bfloat16(vy - __bfloat162float(hy));
                    *(__nv_bfloat162*)(Oh + r * ldc + c) = __nv_bfloat162(hx, hy);
                    *(__nv_bfloat162*)(Ol + r * ldc + c) = __nv_bfloat162(lx, ly);
                }
            }
        }
    }
}

// ---------------------------------------------------------------------------
// Elementwise fp32 -> bf16 hi/lo split (weights only; small)
// ---------------------------------------------------------------------------
__global__ void split_elem(const float* __restrict__ s,
                           __nv_bfloat16* __restrict__ h,
                           __nv_bfloat16* __restrict__ l, long n)
{
    long i = (long)blockIdx.x * blockDim.x + threadIdx.x;
    if (i >= n) return;
    float v = s[i];
    __nv_bfloat16 hi = __float2bfloat16(v);
    h[i] = hi;
    l[i] = __float2bfloat16(v - __bfloat162float(hi));
}

// ---------------------------------------------------------------------------
// Transpose + per-t scale + bf16 split: src[C,T] -> dst[T,C]  (vectorized)
// 32x32 tile, 256 threads. Load: float4 per thread; store: 4 c's per thread,
// packed uint2 writes.
// ---------------------------------------------------------------------------
__global__ void tsplit_kernel(const float* __restrict__ src, long bstride,
                              const float* __restrict__ inv, float scale,
                              __nv_bfloat16* __restrict__ dh,
                              __nv_bfloat16* __restrict__ dl)
{
    __shared__ float tile[32][33];
    const int b   = blockIdx.z;
    const int t0  = blockIdx.x * 32;
    const int c0  = blockIdx.y * 32;
    const int tid = threadIdx.x;
    const float* s = src + (long)b * bstride;

    {
        const int c  = tid >> 3;
        const int tc = tid & 7;
        float4 v = *(const float4*)(s + (long)(c0 + c) * NT + t0 + tc * 4);
        tile[c][tc * 4 + 0] = v.x;
        tile[c][tc * 4 + 1] = v.y;
        tile[c][tc * 4 + 2] = v.z;
        tile[c][tc * 4 + 3] = v.w;
    }
    __syncthreads();

    {
        const int tq  = tid >> 3;          // t within tile
        const int cch = tid & 7;           // 4-channel chunk
        const int tt  = t0 + tq;
        const float sc = scale * (inv ? inv[(long)b * NT + tt] : 1.f);
        float v[4];
#pragma unroll
        for (int i = 0; i < 4; i++) v[i] = tile[cch * 4 + i][tq] * sc;
        uint2 hi, lo;
        split4(v, hi, lo);
        const long o = (long)b * NT * NC + (long)tt * NC + c0 + cch * 4;
        *(uint2*)(dh + o) = hi;
        *(uint2*)(dl + o) = lo;
    }
}

// ---------------------------------------------------------------------------
// Depthwise conv k=3 pad=1 over T (vectorized: 4 t per thread)
// q,k -> fp32 qkv2; v -> bf16 hi/lo packed
// ---------------------------------------------------------------------------
__global__ void dwconv3_kernel(const float* __restrict__ in,
                               const float* __restrict__ w,
                               float* __restrict__ out_qk,
                               __nv_bfloat16* __restrict__ vh,
                               __nv_bfloat16* __restrict__ vl)
{
    const long total4 = (long)NB * N3C * (NT / 4);
    long i4 = (long)blockIdx.x * blockDim.x + threadIdx.x;
    if (i4 >= total4) return;
    const int t4 = (int)(i4 % (NT / 4));
    const int ch = (int)((i4 / (NT / 4)) % N3C);
    const int b  = (int)(i4 / ((long)N3C * (NT / 4)));
    const long base = (long)b * N3C * NT + (long)ch * NT;
    const int t0 = t4 * 4;

    const float4 cur = *(const float4*)(in + base + t0);
    const float prev = (t0 > 0)       ? in[base + t0 - 1] : 0.f;
    const float nxt  = (t0 + 4 < NT)  ? in[base + t0 + 4] : 0.f;
    const float w0 = w[ch * 3 + 0], w1 = w[ch * 3 + 1], w2 = w[ch * 3 + 2];

    float o[4];
    o[0] = w0 * prev  + w1 * cur.x + w2 * cur.y;
    o[1] = w0 * cur.x + w1 * cur.y + w2 * cur.z;
    o[2] = w0 * cur.y + w1 * cur.z + w2 * cur.w;
    o[3] = w0 * cur.z + w1 * cur.w + w2 * nxt;

    if (ch < 2 * NC) {
        *(float4*)(out_qk + (long)b * 2 * NC * NT + (long)ch * NT + t0) =
            make_float4(o[0], o[1], o[2], o[3]);
    } else {
        const long oo = (long)b * NC * NT + (long)(ch - 2 * NC) * NT + t0;
        uint2 hi, lo;
        split4(o, hi, lo);
        *(uint2*)(vh + oo) = hi;
        *(uint2*)(vl + oo) = lo;
    }
}

// ---------------------------------------------------------------------------
// Per-(b,t) inverse L2 norms of q and k channels
// ---------------------------------------------------------------------------
__global__ void norms_kernel(const float* __restrict__ qkv2,
                             float* __restrict__ qinv, float* __restrict__ kinv)
{
    const int b = blockIdx.y;
    const int t = blockIdx.x * 128 + threadIdx.x;
    const float* base = qkv2 + (long)b * 2 * NC * NT;
    float sq = 0.f, sk = 0.f;
#pragma unroll 4
    for (int c = 0; c < NC; c++) {
        float a = base[(long)c * NT + t];          sq += a * a;
        float d = base[(long)(NC + c) * NT + t];   sk += d * d;
    }
    qinv[(long)b * NT + t] = 1.f / fmaxf(sqrtf(sq), L2EPS);
    kinv[(long)b * NT + t] = 1.f / fmaxf(sqrtf(sk), L2EPS);
}

// ---------------------------------------------------------------------------
// Row softmax over T, vectorized float4 loads, packed bf16 hi/lo stores
// ---------------------------------------------------------------------------
__inline__ __device__ float warpMax(float v) {
#pragma unroll
    for (int o = 16; o; o >>= 1) v = fmaxf(v, __shfl_xor_sync(0xffffffffu, v, o));
    return v;
}
__inline__ __device__ float warpSum(float v) {
#pragma unroll
    for (int o = 16; o; o >>= 1) v += __shfl_xor_sync(0xffffffffu, v, o);
    return v;
}

__global__ void softmax_split_kernel(const float* __restrict__ scores,
                                     __nv_bfloat16* __restrict__ ah,
                                     __nv_bfloat16* __restrict__ al)
{
    const long row = blockIdx.x;
    const float4* p4 = (const float4*)(scores + row * NT);
    const int tid  = threadIdx.x;
    const int lane = tid & 31;
    const int wid  = tid >> 5;
    __shared__ float red[8];

    float4 va = p4[tid], vb = p4[tid + 256];
    float vals[8] = {va.x, va.y, va.z, va.w, vb.x, vb.y, vb.z, vb.w};

    float m = -1e30f;
#pragma unroll
    for (int i = 0; i < 8; i++) m = fmaxf(m, vals[i]);
    m = warpMax(m);
    if (lane == 0) red[wid] = m;
    __syncthreads();
    if (wid == 0) {
        float v = (lane < 8) ? red[lane] : -1e30f;
        v = warpMax(v);
        if (lane == 0) red[0] = v;
    }
    __syncthreads();
    m = red[0];
    __syncthreads();

    float s = 0.f;
#pragma unroll
    for (int i = 0; i < 8; i++) { vals[i] = __expf(vals[i] - m); s += vals[i]; }
    s = warpSum(s);
    if (lane == 0) red[wid] = s;
    __syncthreads();
    if (wid == 0) {
        float v = (lane < 8) ? red[lane] : 0.f;
        v = warpSum(v);
        if (lane == 0) red[0] = v;
    }
    __syncthreads();
    const float inv = 1.f / red[0];

#pragma unroll
    for (int g = 0; g < 2; g++) {
        float v[4];
#pragma unroll
        for (int i = 0; i < 4; i++) v[i] = vals[g * 4 + i] * inv;
        uint2 hi, lo;
        split4(v, hi, lo);
        const long o = row * NT + (long)(tid + g * 256) * 4;
        *(uint2*)(ah + o) = hi;
        *(uint2*)(al + o) = lo;
    }
}

// ---------------------------------------------------------------------------
// Launch
// ---------------------------------------------------------------------------
extern "C" void kernel_launch(void* const* d_in, const int* in_sizes, int n_in,
                              void* d_out, int out_size)
{
    const float* x      = (const float*)d_in[0];
    const float* w_qkv  = (const float*)d_in[1];
    const float* w_dw   = (const float*)d_in[2];
    const float* w_proj = (const float*)d_in[3];
    float* out = (float*)d_out;

    cudaFuncSetAttribute(gemm_bf16x3<0>, cudaFuncAttributeMaxDynamicSharedMemorySize, GEMM_SMEM);
    cudaFuncSetAttribute(gemm_bf16x3<1>, cudaFuncAttributeMaxDynamicSharedMemorySize, GEMM_SMEM);

    float *qkv, *qkv2, *scores, *qinv, *kinv;
    cudaGetSymbolAddress((void**)&qkv,    g_qkv);
    cudaGetSymbolAddress((void**)&qkv2,   g_qkv2);
    cudaGetSymbolAddress((void**)&scores, g_scores);
    cudaGetSymbolAddress((void**)&qinv,   g_qinv);
    cudaGetSymbolAddress((void**)&kinv,   g_kinv);

    __nv_bfloat16 *wqh, *wql, *wph, *wpl, *xth, *xtl, *qth, *qtl, *kth, *ktl,
                  *vh, *vl, *ath, *atl, *oth, *otl;
    cudaGetSymbolAddress((void**)&wqh, g_wq_h);  cudaGetSymbolAddress((void**)&wql, g_wq_l);
    cudaGetSymbolAddress((void**)&wph, g_wp_h);  cudaGetSymbolAddress((void**)&wpl, g_wp_l);
    cudaGetSymbolAddress((void**)&xth, g_xT_h);  cudaGetSymbolAddress((void**)&xtl, g_xT_l);
    cudaGetSymbolAddress((void**)&qth, g_qT_h);  cudaGetSymbolAddress((void**)&qtl, g_qT_l);
    cudaGetSymbolAddress((void**)&kth, g_kT_h);  cudaGetSymbolAddress((void**)&ktl, g_kT_l);
    cudaGetSymbolAddress((void**)&vh,  g_v_h);   cudaGetSymbolAddress((void**)&vl,  g_v_l);
    cudaGetSymbolAddress((void**)&ath, g_at_h);  cudaGetSymbolAddress((void**)&atl, g_at_l);
    cudaGetSymbolAddress((void**)&oth, g_oT_h);  cudaGetSymbolAddress((void**)&otl, g_oT_l);

    // weight splits
    split_elem<<<(unsigned)(((long)N3C * NC + 255) / 256), 256>>>(w_qkv, wqh, wql, (long)N3C * NC);
    split_elem<<<(unsigned)(((long)NC * NC + 255) / 256), 256>>>(w_proj, wph, wpl, (long)NC * NC);

    // xT split (transpose [C,T] -> [T,C])
    {
        dim3 grid(NT / 32, NC / 32, NB);
        tsplit_kernel<<<grid, 256>>>(x, (long)NC * NT, nullptr, 1.f, xth, xtl);
    }

    // 1) qkv = W_qkv @ x : M=1536, N=2048, K=512 -> fp32
    {
        dim3 grid(NT / 128, N3C / 128, NB);
        gemm_bf16x3<0><<<grid, 256, GEMM_SMEM>>>(wqh, wql, xth, xtl, qkv, nullptr, nullptr,
            512, NT, 0L, (long)NT * NC, (long)N3C * NT);
    }

    // 2) depthwise conv (q,k -> qkv2 fp32; v -> vh/vl bf16 direct)
    {
        const long total4 = (long)NB * N3C * (NT / 4);
        dwconv3_kernel<<<(unsigned)((total4 + 255) / 256), 256>>>(qkv, w_dw, qkv2, vh, vl);
    }

    // 3) inverse norms for q, k
    norms_kernel<<<dim3(NT / 128, NB), 128>>>(qkv2, qinv, kinv);

    // 4) qT/kT transpose-split with fused normalization (+TEMP on q)
    {
        dim3 grid(NT / 32, NC / 32, NB);
        tsplit_kernel<<<grid, 256>>>(qkv2, (long)2 * NC * NT, qinv, TEMP_INV, qth, qtl);
        tsplit_kernel<<<grid, 256>>>(qkv2 + (long)NC * NT, (long)2 * NC * NT, kinv, 1.f, kth, ktl);
    }

    // 5) scores = qT @ kT^T : M=N=2048, K=512 -> fp32
    {
        dim3 grid(NT / 128, NT / 128, NB);
        gemm_bf16x3<0><<<grid, 256, GEMM_SMEM>>>(qth, qtl, kth, ktl, scores, nullptr, nullptr,
            512, NT, (long)NT * NC, (long)NT * NC, (long)NT * NT);
    }

    // 6) softmax + bf16 split
    softmax_split_kernel<<<NB * NT, 256>>>(scores, ath, atl);

    // 7) outT = attn @ v^T : M=2048, N=512, K=2048 -> bf16 hi/lo direct
    {
        dim3 grid(NC / 128, NT / 128, NB);
        gemm_bf16x3<1><<<grid, 256, GEMM_SMEM>>>(ath, atl, vh, vl, nullptr, oth, otl,
            2048, NC, (long)NT * NT, (long)NC * NT, (long)NT * NC);
    }

    // 8) final = W_proj @ outT^T : M=512, N=2048, K=512 -> fp32 d_out
    {
        dim3 grid(NT / 128, NC / 128, NB);
        gemm_bf16x3<0><<<grid, 256, GEMM_SMEM>>>(wph, wpl, oth, otl, out, nullptr, nullptr,
            512, NT, 0L, (long)NT * NC, (long)NC * NT);
    }
}

// round 12
// speedup vs baseline: 3.1052x; 1.0862x over previous
#include <cuda_runtime.h>
#include <cuda_bf16.h>
#include <math.h>
#include <stdint.h>

// Problem constants
#define NB 8
#define NC 512
#define NT 2048
#define N3C 1536
#define TEMP_INV (1.0f / 0.07f)
#define L2EPS 1e-12f

// ---------------------------------------------------------------------------
// Static scratch (no allocation allowed anywhere)
// ---------------------------------------------------------------------------
__device__ float g_qkv   [(size_t)NB * N3C * NT];
__device__ float g_scores[(size_t)NB * NT  * NT];

__device__ __nv_bfloat16 g_wq_h[(size_t)N3C * NC], g_wq_l[(size_t)N3C * NC];
__device__ __nv_bfloat16 g_wp_h[(size_t)NC  * NC], g_wp_l[(size_t)NC  * NC];
__device__ __nv_bfloat16 g_xT_h[(size_t)NB * NT * NC], g_xT_l[(size_t)NB * NT * NC];
__device__ __nv_bfloat16 g_qT_h[(size_t)NB * NT * NC], g_qT_l[(size_t)NB * NT * NC];
__device__ __nv_bfloat16 g_kT_h[(size_t)NB * NT * NC], g_kT_l[(size_t)NB * NT * NC];
__device__ __nv_bfloat16 g_v_h [(size_t)NB * NC * NT], g_v_l [(size_t)NB * NC * NT];
__device__ __nv_bfloat16 g_at_h[(size_t)NB * NT * NT], g_at_l[(size_t)NB * NT * NT];
__device__ __nv_bfloat16 g_oT_h[(size_t)NB * NT * NC], g_oT_l[(size_t)NB * NT * NC];

// ---------------------------------------------------------------------------
// PTX helpers (baseline sm_80+ only)
// ---------------------------------------------------------------------------
__device__ __forceinline__ uint32_t s2u(const void* p) {
    uint32_t a;
    asm("{ .reg .u64 t; cvta.to.shared.u64 t, %1; cvt.u32.u64 %0, t; }"
        : "=r"(a) : "l"(p));
    return a;
}

__device__ __forceinline__ void cp16(uint32_t s, const void* g) {
    asm volatile("cp.async.cg.shared.global [%0], [%1], 16;" :: "r"(s), "l"(g));
}
#define CP_COMMIT() asm volatile("cp.async.commit_group;" ::: "memory")
#define CP_WAIT(n)  asm volatile("cp.async.wait_group %0;" :: "n"(n) : "memory")

__device__ __forceinline__ void ldsm4(uint32_t* r, uint32_t a) {
    asm volatile("ldmatrix.sync.aligned.m8n8.x4.shared.b16 {%0,%1,%2,%3}, [%4];"
                 : "=r"(r[0]), "=r"(r[1]), "=r"(r[2]), "=r"(r[3]) : "r"(a));
}

__device__ __forceinline__ void mma16816(float* c, const uint32_t* a, const uint32_t* b) {
    asm volatile(
        "mma.sync.aligned.m16n8k16.row.col.f32.bf16.bf16.f32 "
        "{%0,%1,%2,%3}, {%4,%5,%6,%7}, {%8,%9}, {%0,%1,%2,%3};"
        : "+f"(c[0]), "+f"(c[1]), "+f"(c[2]), "+f"(c[3])
        : "r"(a[0]), "r"(a[1]), "r"(a[2]), "r"(a[3]), "r"(b[0]), "r"(b[1]));
}

// 128-byte-row XOR swizzle
__device__ __forceinline__ uint32_t swz(uint32_t b) {
    return b ^ (((b >> 7) & 7) << 4);
}

__device__ __forceinline__ void split4(const float* v, uint2& hi, uint2& lo) {
    __nv_bfloat16 h0 = __float2bfloat16(v[0]);
    __nv_bfloat16 h1 = __float2bfloat16(v[1]);
    __nv_bfloat16 h2 = __float2bfloat16(v[2]);
    __nv_bfloat16 h3 = __float2bfloat16(v[3]);
    __nv_bfloat162 a = __nv_bfloat162(h0, h1), b = __nv_bfloat162(h2, h3);
    hi.x = *(uint32_t*)&a;  hi.y = *(uint32_t*)&b;
    __nv_bfloat162 c = __nv_bfloat162(__float2bfloat16(v[0] - __bfloat162float(h0)),
                                      __float2bfloat16(v[1] - __bfloat162float(h1)));
    __nv_bfloat162 d = __nv_bfloat162(__float2bfloat16(v[2] - __bfloat162float(h2)),
                                      __float2bfloat16(v[3] - __bfloat162float(h3)));
    lo.x = *(uint32_t*)&c;  lo.y = *(uint32_t*)&d;
}

__inline__ __device__ float warpMax(float v) {
#pragma unroll
    for (int o = 16; o; o >>= 1) v = fmaxf(v, __shfl_xor_sync(0xffffffffu, v, o));
    return v;
}
__inline__ __device__ float warpSum(float v) {
#pragma unroll
    for (int o = 16; o; o >>= 1) v += __shfl_xor_sync(0xffffffffu, v, o);
    return v;
}

// ---------------------------------------------------------------------------
// bf16x3 GEMM (unchanged, stable at tensor=66%)
// ---------------------------------------------------------------------------
#define STAGE_BYTES 32768
#define NSTAGE 3
#define GEMM_SMEM (NSTAGE * STAGE_BYTES)   // 96 KB -> 2 CTAs/SM

template <int OUT>
__global__ __launch_bounds__(256, 2)
void gemm_bf16x3(const __nv_bfloat16* __restrict__ Ah, const __nv_bfloat16* __restrict__ Al,
                 const __nv_bfloat16* __restrict__ Bh, const __nv_bfloat16* __restrict__ Bl,
                 float* __restrict__ C,
                 __nv_bfloat16* __restrict__ Oh, __nv_bfloat16* __restrict__ Ol,
                 int K, int ldc, long sA, long sB, long sC)
{
    extern __shared__ __align__(1024) char smem[];
    const uint32_t sb = s2u(smem);
    const int tid  = threadIdx.x;
    const int lane = tid & 31;
    const int wid  = tid >> 5;
    const int wm   = wid & 1;
    const int wn   = wid >> 1;
    const long bm  = (long)blockIdx.y * 128;
    const long bn  = (long)blockIdx.x * 128;

    Ah += blockIdx.z * sA + bm * K;  Al += blockIdx.z * sA + bm * K;
    Bh += blockIdx.z * sB + bn * K;  Bl += blockIdx.z * sB + bn * K;

    const int NS = K >> 5;

    float acc[4][4][4];
#pragma unroll
    for (int mi = 0; mi < 4; mi++)
#pragma unroll
        for (int ni = 0; ni < 4; ni++)
#pragma unroll
            for (int r = 0; r < 4; r++) acc[mi][ni][r] = 0.f;

    auto load_stage = [&](int kb, int slot) {
        const uint32_t st = sb + slot * STAGE_BYTES;
        const long gk = (long)kb * 32;
#pragma unroll
        for (int j = 0; j < 2; j++) {
            const int c   = tid + j * 256;
            const int row = c >> 2;
            const int kc  = c & 3;
            const uint32_t so =
                swz((uint32_t)((row & 63) * 128 + (row >> 6) * 64 + kc * 16));
            const long go = (long)row * K + gk + kc * 8;
            cp16(st +          so, Ah + go);
            cp16(st +  8192 +  so, Al + go);
            cp16(st + 16384 +  so, Bh + go);
            cp16(st + 24576 +  so, Bl + go);
        }
    };

    auto b_addr = [&](uint32_t st, int ks, int nipair) -> uint32_t {
        const int g = lane >> 3, l = lane & 7;
        const int n = wn * 32 + nipair * 16 + (g >> 1) * 8 + l;
        const uint32_t kbyte = (uint32_t)(ks * 32 + (g & 1) * 16);
        return st + swz((uint32_t)((n & 63) * 128 + (n >> 6) * 64) + kbyte);
    };

    auto compute_stage = [&](int slot) {
        const uint32_t st = sb + slot * STAGE_BYTES;
#pragma unroll
        for (int ks = 0; ks < 2; ks++) {
            uint32_t bhf[2][4], blf[2][4];
#pragma unroll
            for (int np = 0; np < 2; np++) {
                const uint32_t ba = b_addr(st, ks, np);
                ldsm4(bhf[np], 16384 + ba);
                ldsm4(blf[np],  24576 + ba);
            }
#pragma unroll
            for (int mi = 0; mi < 4; mi++) {
                uint32_t ahf[4], alf[4];
                const uint32_t off = swz((uint32_t)(
                    (mi * 16 + (lane & 15)) * 128 + wm * 64 + ks * 32 + ((lane >> 4) << 4)));
                ldsm4(ahf, st + off);
                ldsm4(alf, st + 8192 + off);
#pragma unroll
                for (int ni = 0; ni < 4; ni++) {
                    const uint32_t* bh = &bhf[ni >> 1][(ni & 1) * 2];
                    const uint32_t* bl = &blf[ni >> 1][(ni & 1) * 2];
                    mma16816(acc[mi][ni], ahf, bh);
                    mma16816(acc[mi][ni], ahf, bl);
                    mma16816(acc[mi][ni], alf, bh);
                }
            }
        }
    };

    load_stage(0, 0); CP_COMMIT();
    load_stage(1, 1); CP_COMMIT();

    for (int kb = 0; kb < NS; kb++) {
        CP_WAIT(1);
        __syncthreads();
        if (kb + 2 < NS) load_stage(kb + 2, (kb + 2) % 3);
        CP_COMMIT();
        compute_stage(kb % 3);
    }

    if (OUT == 0) {
        C += blockIdx.z * sC;
#pragma unroll
        for (int mi = 0; mi < 4; mi++) {
            const long r0 = bm + wm * 64 + mi * 16 + (lane >> 2);
#pragma unroll
            for (int ni = 0; ni < 4; ni++) {
                const long c = bn + wn * 32 + ni * 8 + (lane & 3) * 2;
                *(float2*)(C + r0 * ldc + c) =
                    make_float2(acc[mi][ni][0], acc[mi][ni][1]);
                *(float2*)(C + (r0 + 8) * ldc + c) =
                    make_float2(acc[mi][ni][2], acc[mi][ni][3]);
            }
        }
    } else {
        Oh += blockIdx.z * sC;  Ol += blockIdx.z * sC;
#pragma unroll
        for (int mi = 0; mi < 4; mi++) {
            const long r0 = bm + wm * 64 + mi * 16 + (lane >> 2);
#pragma unroll
            for (int ni = 0; ni < 4; ni++) {
                const long c = bn + wn * 32 + ni * 8 + (lane & 3) * 2;
#pragma unroll
                for (int p = 0; p < 2; p++) {
                    const long r = r0 + p * 8;
                    float vx = acc[mi][ni][2 * p], vy = acc[mi][ni][2 * p + 1];
                    __nv_bfloat16 hx = __float2bfloat16(vx);
                    __nv_bfloat16 hy = __float2bfloat16(vy);
                    __nv_bfloat16 lx = __float2bfloat16(vx - __bfloat162float(hx));
                    __nv_bfloat16 ly = __float2bfloat16(vy - __bfloat162float(hy));
                    *(__nv_bfloat162*)(Oh + r * ldc + c) = __nv_bfloat162(hx, hy);
                    *(__nv_bfloat162*)(Ol + r * ldc + c) = __nv_bfloat162(lx, ly);
                }
            }
        }
    }
}

// ---------------------------------------------------------------------------
// Elementwise fp32 -> bf16 hi/lo split (weights only)
// ---------------------------------------------------------------------------
__global__ void split_elem(const float* __restrict__ s,
                           __nv_bfloat16* __restrict__ h,
                           __nv_bfloat16* __restrict__ l, long n)
{
    long i = (long)blockIdx.x * blockDim.x + threadIdx.x;
    if (i >= n) return;
    float v = s[i];
    __nv_bfloat16 hi = __float2bfloat16(v);
    h[i] = hi;
    l[i] = __float2bfloat16(v - __bfloat162float(hi));
}

// ---------------------------------------------------------------------------
// Transpose + bf16 split for input x: src[C,T] -> dst[T,C]
// ---------------------------------------------------------------------------
__global__ void tsplit_kernel(const float* __restrict__ src,
                              __nv_bfloat16* __restrict__ dh,
                              __nv_bfloat16* __restrict__ dl)
{
    __shared__ float tile[32][33];
    const int b   = blockIdx.z;
    const int t0  = blockIdx.x * 32;
    const int c0  = blockIdx.y * 32;
    const int tid = threadIdx.x;
    const float* s = src + (long)b * NC * NT;

    {
        const int c  = tid >> 3;
        const int tc = tid & 7;
        float4 v = *(const float4*)(s + (long)(c0 + c) * NT + t0 + tc * 4);
        tile[c][tc * 4 + 0] = v.x;
        tile[c][tc * 4 + 1] = v.y;
        tile[c][tc * 4 + 2] = v.z;
        tile[c][tc * 4 + 3] = v.w;
    }
    __syncthreads();

    {
        const int tq  = tid >> 3;
        const int cch = tid & 7;
        const int tt  = t0 + tq;
        float v[4];
#pragma unroll
        for (int i = 0; i < 4; i++) v[i] = tile[cch * 4 + i][tq];
        uint2 hi, lo;
        split4(v, hi, lo);
        const long o = (long)b * NT * NC + (long)tt * NC + c0 + cch * 4;
        *(uint2*)(dh + o) = hi;
        *(uint2*)(dl + o) = lo;
    }
}

// ---------------------------------------------------------------------------
// FUSED q/k path: dwconv + per-token L2 norm + scaled transpose + bf16 split.
// grid(NT/32, NB, 2): z=0 -> q (scale TEMP_INV), z=1 -> k.
// smem tile[32 t][513 pad] fp32 (66 KB dynamic).
// ---------------------------------------------------------------------------
#define QK_SMEM (32 * 513 * 4 + 128)

__global__ __launch_bounds__(256)
void qk_fuse_kernel(const float* __restrict__ qkv,
                    const float* __restrict__ w,
                    __nv_bfloat16* __restrict__ qh, __nv_bfloat16* __restrict__ ql,
                    __nv_bfloat16* __restrict__ kh, __nv_bfloat16* __restrict__ kl)
{
    extern __shared__ float smf[];
    float (*tile)[513] = (float (*)[513])smf;
    float* sinv = smf + 32 * 513;

    const int sel = blockIdx.z;        // 0=q, 1=k
    const int b   = blockIdx.y;
    const int t0  = blockIdx.x * 32;
    const int tid = threadIdx.x;
    const int lane = tid & 31;
    const int wid  = tid >> 5;

    const float* src = qkv + (long)b * N3C * NT + (long)sel * NC * NT;
    const float* wch = w + (long)sel * NC * 3;

    // Phase 1: dwconv into smem (transposed layout tile[t][c])
#pragma unroll
    for (int it = 0; it < 16; it++) {
        const int idx = tid + it * 256;      // 0..4095
        const int c   = idx >> 3;
        const int t4  = idx & 7;
        const long base = (long)c * NT + t0 + t4 * 4;
        const int tg = t0 + t4 * 4;
        const float4 cur = *(const float4*)(src + base);
        const float prev = (tg > 0)       ? src[base - 1] : 0.f;
        const float nxt  = (tg + 4 < NT)  ? src[base + 4] : 0.f;
        const float w0 = wch[c * 3 + 0], w1 = wch[c * 3 + 1], w2 = wch[c * 3 + 2];
        tile[t4 * 4 + 0][c] = w0 * prev  + w1 * cur.x + w2 * cur.y;
        tile[t4 * 4 + 1][c] = w0 * cur.x + w1 * cur.y + w2 * cur.z;
        tile[t4 * 4 + 2][c] = w0 * cur.y + w1 * cur.z + w2 * cur.w;
        tile[t4 * 4 + 3][c] = w0 * cur.z + w1 * cur.w + w2 * nxt;
    }
    __syncthreads();

    // Phase 2: inverse L2 norm per t (warp w handles t = w*4..w*4+3)
    const float scale0 = (sel == 0) ? TEMP_INV : 1.f;
#pragma unroll
    for (int j = 0; j < 4; j++) {
        const int t = wid * 4 + j;
        float s = 0.f;
#pragma unroll
        for (int u = 0; u < 16; u++) {
            const float v = tile[t][lane + u * 32];
            s += v * v;
        }
        s = warpSum(s);
        if (lane == 0) sinv[t] = scale0 / fmaxf(sqrtf(s), L2EPS);
    }
    __syncthreads();

    // Phase 3: scaled transpose-split write [t][c]
    __nv_bfloat16* dh = (sel == 0) ? qh : kh;
    __nv_bfloat16* dl = (sel == 0) ? ql : kl;
    const int t  = tid >> 3;
    const int c8 = tid & 7;
    const float sc = sinv[t];
    const long orow = (long)b * NT * NC + (long)(t0 + t) * NC;
#pragma unroll
    for (int it = 0; it < 16; it++) {
        const int c = (c8 + it * 8) * 4;
        float v[4];
#pragma unroll
        for (int i = 0; i < 4; i++) v[i] = tile[t][c + i] * sc;
        uint2 hi, lo;
        split4(v, hi, lo);
        *(uint2*)(dh + orow + c) = hi;
        *(uint2*)(dl + orow + c) = lo;
    }
}

// ---------------------------------------------------------------------------
// Depthwise conv for V channels only -> bf16 hi/lo packed
// ---------------------------------------------------------------------------
__global__ void vdw_kernel(const float* __restrict__ qkv,
                           const float* __restrict__ w,
                           __nv_bfloat16* __restrict__ vh,
                           __nv_bfloat16* __restrict__ vl)
{
    const long total4 = (long)NB * NC * (NT / 4);
    long i4 = (long)blockIdx.x * blockDim.x + threadIdx.x;
    if (i4 >= total4) return;
    const int t4 = (int)(i4 % (NT / 4));
    const int ch = (int)((i4 / (NT / 4)) % NC);
    const int b  = (int)(i4 / ((long)NC * (NT / 4)));
    const long base = (long)b * N3C * NT + (long)(2 * NC + ch) * NT;
    const int t0 = t4 * 4;

    const float4 cur = *(const float4*)(qkv + base + t0);
    const float prev = (t0 > 0)       ? qkv[base + t0 - 1] : 0.f;
    const float nxt  = (t0 + 4 < NT)  ? qkv[base + t0 + 4] : 0.f;
    const int wc = (2 * NC + ch) * 3;
    const float w0 = w[wc + 0], w1 = w[wc + 1], w2 = w[wc + 2];

    float o[4];
    o[0] = w0 * prev  + w1 * cur.x + w2 * cur.y;
    o[1] = w0 * cur.x + w1 * cur.y + w2 * cur.z;
    o[2] = w0 * cur.y + w1 * cur.z + w2 * cur.w;
    o[3] = w0 * cur.z + w1 * cur.w + w2 * nxt;

    const long oo = (long)b * NC * NT + (long)ch * NT + t0;
    uint2 hi, lo;
    split4(o, hi, lo);
    *(uint2*)(vh + oo) = hi;
    *(uint2*)(vl + oo) = lo;
}

// ---------------------------------------------------------------------------
// Row softmax over T, float4 loads, packed bf16 hi/lo stores
// ---------------------------------------------------------------------------
__global__ void softmax_split_kernel(const float* __restrict__ scores,
                                     __nv_bfloat16* __restrict__ ah,
                                     __nv_bfloat16* __restrict__ al)
{
    const long row = blockIdx.x;
    const float4* p4 = (const float4*)(scores + row * NT);
    const int tid  = threadIdx.x;
    const int lane = tid & 31;
    const int wid  = tid >> 5;
    __shared__ float red[8];

    float4 va = p4[tid], vb = p4[tid + 256];
    float vals[8] = {va.x, va.y, va.z, va.w, vb.x, vb.y, vb.z, vb.w};

    float m = -1e30f;
#pragma unroll
    for (int i = 0; i < 8; i++) m = fmaxf(m, vals[i]);
    m = warpMax(m);
    if (lane == 0) red[wid] = m;
    __syncthreads();
    if (wid == 0) {
        float v = (lane < 8) ? red[lane] : -1e30f;
        v = warpMax(v);
        if (lane == 0) red[0] = v;
    }
    __syncthreads();
    m = red[0];
    __syncthreads();

    float s = 0.f;
#pragma unroll
    for (int i = 0; i < 8; i++) { vals[i] = __expf(vals[i] - m); s += vals[i]; }
    s = warpSum(s);
    if (lane == 0) red[wid] = s;
    __syncthreads();
    if (wid == 0) {
        float v = (lane < 8) ? red[lane] : 0.f;
        v = warpSum(v);
        if (lane == 0) red[0] = v;
    }
    __syncthreads();
    const float inv = 1.f / red[0];

#pragma unroll
    for (int g = 0; g < 2; g++) {
        float v[4];
#pragma unroll
        for (int i = 0; i < 4; i++) v[i] = vals[g * 4 + i] * inv;
        uint2 hi, lo;
        split4(v, hi, lo);
        const long o = row * NT + (long)(tid + g * 256) * 4;
        *(uint2*)(ah + o) = hi;
        *(uint2*)(al + o) = lo;
    }
}

// ---------------------------------------------------------------------------
// Launch
// ---------------------------------------------------------------------------
extern "C" void kernel_launch(void* const* d_in, const int* in_sizes, int n_in,
                              void* d_out, int out_size)
{
    const float* x      = (const float*)d_in[0];
    const float* w_qkv  = (const float*)d_in[1];
    const float* w_dw   = (const float*)d_in[2];
    const float* w_proj = (const float*)d_in[3];
    float* out = (float*)d_out;

    cudaFuncSetAttribute(gemm_bf16x3<0>, cudaFuncAttributeMaxDynamicSharedMemorySize, GEMM_SMEM);
    cudaFuncSetAttribute(gemm_bf16x3<1>, cudaFuncAttributeMaxDynamicSharedMemorySize, GEMM_SMEM);
    cudaFuncSetAttribute(qk_fuse_kernel, cudaFuncAttributeMaxDynamicSharedMemorySize, QK_SMEM);

    float *qkv, *scores;
    cudaGetSymbolAddress((void**)&qkv,    g_qkv);
    cudaGetSymbolAddress((void**)&scores, g_scores);

    __nv_bfloat16 *wqh, *wql, *wph, *wpl, *xth, *xtl, *qth, *qtl, *kth, *ktl,
                  *vh, *vl, *ath, *atl, *oth, *otl;
    cudaGetSymbolAddress((void**)&wqh, g_wq_h);  cudaGetSymbolAddress((void**)&wql, g_wq_l);
    cudaGetSymbolAddress((void**)&wph, g_wp_h);  cudaGetSymbolAddress((void**)&wpl, g_wp_l);
    cudaGetSymbolAddress((void**)&xth, g_xT_h);  cudaGetSymbolAddress((void**)&xtl, g_xT_l);
    cudaGetSymbolAddress((void**)&qth, g_qT_h);  cudaGetSymbolAddress((void**)&qtl, g_qT_l);
    cudaGetSymbolAddress((void**)&kth, g_kT_h);  cudaGetSymbolAddress((void**)&ktl, g_kT_l);
    cudaGetSymbolAddress((void**)&vh,  g_v_h);   cudaGetSymbolAddress((void**)&vl,  g_v_l);
    cudaGetSymbolAddress((void**)&ath, g_at_h);  cudaGetSymbolAddress((void**)&atl, g_at_l);
    cudaGetSymbolAddress((void**)&oth, g_oT_h);  cudaGetSymbolAddress((void**)&otl, g_oT_l);

    // weight splits
    split_elem<<<(unsigned)(((long)N3C * NC + 255) / 256), 256>>>(w_qkv, wqh, wql, (long)N3C * NC);
    split_elem<<<(unsigned)(((long)NC * NC + 255) / 256), 256>>>(w_proj, wph, wpl, (long)NC * NC);

    // xT split (transpose [C,T] -> [T,C])
    {
        dim3 grid(NT / 32, NC / 32, NB);
        tsplit_kernel<<<grid, 256>>>(x, xth, xtl);
    }

    // 1) qkv = W_qkv @ x : M=1536, N=2048, K=512 -> fp32
    {
        dim3 grid(NT / 128, N3C / 128, NB);
        gemm_bf16x3<0><<<grid, 256, GEMM_SMEM>>>(wqh, wql, xth, xtl, qkv, nullptr, nullptr,
            512, NT, 0L, (long)NT * NC, (long)N3C * NT);
    }

    // 2) fused dwconv + L2norm + transpose-split for q,k
    {
        dim3 grid(NT / 32, NB, 2);
        qk_fuse_kernel<<<grid, 256, QK_SMEM>>>(qkv, w_dw, qth, qtl, kth, ktl);
    }

    // 3) dwconv for v -> bf16 hi/lo
    {
        const long total4 = (long)NB * NC * (NT / 4);
        vdw_kernel<<<(unsigned)((total4 + 255) / 256), 256>>>(qkv, w_dw, vh, vl);
    }

    // 4) scores = qT @ kT^T : M=N=2048, K=512 -> fp32
    {
        dim3 grid(NT / 128, NT / 128, NB);
        gemm_bf16x3<0><<<grid, 256, GEMM_SMEM>>>(qth, qtl, kth, ktl, scores, nullptr, nullptr,
            512, NT, (long)NT * NC, (long)NT * NC, (long)NT * NT);
    }

    // 5) softmax + bf16 split
    softmax_split_kernel<<<NB * NT, 256>>>(scores, ath, atl);

    // 6) outT = attn @ v^T : M=2048, N=512, K=2048 -> bf16 hi/lo direct
    {
        dim3 grid(NC / 128, NT / 128, NB);
        gemm_bf16x3<1><<<grid, 256, GEMM_SMEM>>>(ath, atl, vh, vl, nullptr, oth, otl,
            2048, NC, (long)NT * NT, (long)NC * NT, (long)NT * NC);
    }

    // 7) final = W_proj @ outT^T : M=512, N=2048, K=512 -> fp32 d_out
    {
        dim3 grid(NT / 128, NC / 128, NB);
        gemm_bf16x3<0><<<grid, 256, GEMM_SMEM>>>(wph, wpl, oth, otl, out, nullptr, nullptr,
            512, NT, 0L, (long)NT * NC, (long)NC * NT);
    }
}